// round 13
// baseline (speedup 1.0000x reference)
#include <cuda_runtime.h>
#include <cuda_bf16.h>
#include <cstdint>
#include <math.h>

// Problem constants (fixed by setup_inputs)
#define DIMC   1024
#define NHC    16
#define HDC    64
#define FQ     16          // frames
#define SQ     1472        // tokens per frame
#define TROWS  (FQ * SQ)   // 23552 total rows
#define WINDOW 8

// ---------------- scratch (device globals; no allocation allowed) ----------
__device__ float g_q[(size_t)TROWS * DIMC];
__device__ float g_k[(size_t)TROWS * DIMC];
__device__ float g_v[(size_t)TROWS * DIMC];
__device__ float g_o[(size_t)TROWS * DIMC];     // tf32-rounded attn output
__device__ float g_x[(size_t)TROWS * DIMC];     // tf32-rounded x
__device__ float g_w[4][DIMC * DIMC];           // tf32-rounded weights q,k,v,o
__device__ float g_ssq[TROWS];
__device__ float g_ssk[TROWS];

// =================== helpers ================================================
__device__ __forceinline__ uint32_t smem_u32(const void* p) {
    uint32_t a;
    asm("{ .reg .u64 t; cvta.to.shared.u64 t, %1; cvt.u32.u64 %0, t; }"
        : "=r"(a) : "l"(p));
    return a;
}

#define CP_ASYNC16(dst, src) \
    asm volatile("cp.async.cg.shared.global [%0], [%1], 16;" \
                 :: "r"(dst), "l"(src) : "memory")
#define CP_COMMIT() asm volatile("cp.async.commit_group;" ::: "memory")
#define CP_WAIT(n)  asm volatile("cp.async.wait_group %0;" :: "n"(n) : "memory")

__device__ __forceinline__ float f2tf32f(float x) {
    uint32_t u;
    asm("cvt.rna.tf32.f32 %0, %1;" : "=r"(u) : "f"(x));
    return __uint_as_float(u);
}

__device__ __forceinline__ void mma_tf32(float* c, const uint32_t* a,
                                         const uint32_t* b) {
    asm volatile(
        "mma.sync.aligned.m16n8k8.row.col.f32.tf32.tf32.f32 "
        "{%0,%1,%2,%3}, {%4,%5,%6,%7}, {%8,%9}, {%0,%1,%2,%3};"
        : "+f"(c[0]), "+f"(c[1]), "+f"(c[2]), "+f"(c[3])
        : "r"(a[0]), "r"(a[1]), "r"(a[2]), "r"(a[3]),
          "r"(b[0]), "r"(b[1]));
}

// ---------------- tf32 rounding prepasses -----------------------------------
__global__ __launch_bounds__(256)
void round_tf32_kernel(const float* __restrict__ in, float* __restrict__ out,
                       int n4)
{
    const int i = blockIdx.x * blockDim.x + threadIdx.x;
    if (i < n4) {
        float4 v = *(const float4*)&in[(size_t)i * 4];
        v.x = f2tf32f(v.x);
        v.y = f2tf32f(v.y);
        v.z = f2tf32f(v.z);
        v.w = f2tf32f(v.w);
        *(float4*)&out[(size_t)i * 4] = v;
    }
}

// batched: round the 4 weight matrices in one launch (blockIdx.y selects)
__global__ __launch_bounds__(256)
void round_w_kernel(const float* __restrict__ w0, const float* __restrict__ w1,
                    const float* __restrict__ w2, const float* __restrict__ w3,
                    float* __restrict__ out /* g_w base */, int n4)
{
    const int m = blockIdx.y;
    const float* in = (m == 0) ? w0 : (m == 1) ? w1 : (m == 2) ? w2 : w3;
    float* o = out + (size_t)m * (DIMC * DIMC);
    const int i = blockIdx.x * blockDim.x + threadIdx.x;
    if (i < n4) {
        float4 v = *(const float4*)&in[(size_t)i * 4];
        v.x = f2tf32f(v.x);
        v.y = f2tf32f(v.y);
        v.z = f2tf32f(v.z);
        v.w = f2tf32f(v.w);
        *(float4*)&o[(size_t)i * 4] = v;
    }
}

// =================== mma.sync TF32 GEMM core ================================
// C[128 rows, 256 cols] block tile, BK=32, 4-stage cp.async pipeline
// (prefetch distance 3), 256 threads, 8 warps with 64x64 warp tiles.
// Fragments double-buffered in registers across k-steps: LDS for ks+1
// issues before the 32-MMA chain of ks (hides LDS latency under HMMA).
// Crossbar traffic: A 16K*4 + B 32K*2 = 128KB / K-tile = 1024 cyc = HMMA floor.
#define GSTAGES      4
#define KT           32
#define KITERS       (DIMC / KT)             // 32
#define A_TILE_BYTES 16384                   // 128 rows x 32 floats
#define B_TILE_BYTES 32768                   // 256 rows x 32 floats
#define STAGE_BYTES  (A_TILE_BYTES + B_TILE_BYTES)   // 48 KB
#define DSMEM_BYTES  (GSTAGES * STAGE_BYTES)         // 192 KB
#define A_TILE_WORDS (A_TILE_BYTES / 4)

__device__ __forceinline__
void gemm_body(const float* __restrict__ A,
               const float* __restrict__ W,
               const float* __restrict__ bias,
               float* __restrict__ C,
               float* __restrict__ ss,
               int bm, int bn, char* dsm)
{
    const uint32_t* su = (const uint32_t*)dsm;

    const int tid  = threadIdx.x;
    const int wid  = tid >> 5;
    const int lane = tid & 31;
    const int q    = lane >> 2;   // 0..7
    const int r    = lane & 3;    // 0..3
    const int wm   = wid & 1;     // warp m block (64 rows of 128)
    const int wn   = wid >> 1;    // warp n block (64 cols of 256)

    const uint32_t sbase = smem_u32(dsm);

    float acc[4][8][4];
#pragma unroll
    for (int f = 0; f < 4; ++f)
#pragma unroll
        for (int j = 0; j < 8; ++j)
#pragma unroll
            for (int c = 0; c < 4; ++c) acc[f][j][c] = 0.f;

    // stage loader: A tile 128x32 (1024 f4) + B tile 256x32 (2048 f4),
    // 256 threads: 4 A-chunks + 8 B-chunks each, swizzled 16B stores
    auto issue_stage = [&](int kt_idx, int buf) {
        const int k0 = kt_idx * KT;
        const uint32_t ab = sbase + buf * STAGE_BYTES;
        const uint32_t bb = ab + A_TILE_BYTES;
#pragma unroll
        for (int it = 0; it < 4; ++it) {
            const int e   = tid + it * 256;    // 0..1023
            const int row = e >> 3;
            const int g   = e & 7;
            const uint32_t off = (uint32_t)(row * 128 + ((g ^ (row & 7)) << 4));
            CP_ASYNC16(ab + off, &A[(size_t)(bm + row) * DIMC + k0 + g * 4]);
        }
#pragma unroll
        for (int it = 0; it < 8; ++it) {
            const int e   = tid + it * 256;    // 0..2047
            const int row = e >> 3;
            const int g   = e & 7;
            const uint32_t off = (uint32_t)(row * 128 + ((g ^ (row & 7)) << 4));
            CP_ASYNC16(bb + off, &W[(size_t)(bn + row) * DIMC + k0 + g * 4]);
        }
        CP_COMMIT();
    };

    issue_stage(0, 0);
    issue_stage(1, 1);
    issue_stage(2, 2);

    uint32_t afr[2][4][4];
    uint32_t bfr[2][8][2];

    for (int kt = 0; kt < KITERS; ++kt) {
        if (kt < KITERS - 2) { CP_WAIT(2); } else { CP_WAIT(0); }
        __syncthreads();
        if (kt + 3 < KITERS) issue_stage(kt + 3, (kt + 3) & (GSTAGES - 1));

        const int buf = kt & (GSTAGES - 1);
        const uint32_t* sA = su + (size_t)buf * (STAGE_BYTES / 4);
        const uint32_t* sB = sA + A_TILE_WORDS;

        // prime: fragments for ks=0 into slot 0
        {
            const int sw0 = (0 ^ q) * 4 + r;
            const int sw1 = (1 ^ q) * 4 + r;
#pragma unroll
            for (int f = 0; f < 4; ++f) {
                const int row0 = wm * 64 + f * 16 + q;     // row%8 == q
                const int row1 = row0 + 8;
                afr[0][f][0] = sA[row0 * 32 + sw0];
                afr[0][f][1] = sA[row1 * 32 + sw0];
                afr[0][f][2] = sA[row0 * 32 + sw1];
                afr[0][f][3] = sA[row1 * 32 + sw1];
            }
#pragma unroll
            for (int j = 0; j < 8; ++j) {
                const int n0 = wn * 64 + j * 8 + q;        // n%8 == q
                bfr[0][j][0] = sB[n0 * 32 + sw0];
                bfr[0][j][1] = sB[n0 * 32 + sw1];
            }
        }

#pragma unroll
        for (int ks = 0; ks < 4; ++ks) {
            const int cur = ks & 1;
            const int nxt = cur ^ 1;
            if (ks < 3) {
                const int g0  = 2 * (ks + 1);
                const int sw0 = (g0 ^ q) * 4 + r;
                const int sw1 = ((g0 + 1) ^ q) * 4 + r;
#pragma unroll
                for (int f = 0; f < 4; ++f) {
                    const int row0 = wm * 64 + f * 16 + q;
                    const int row1 = row0 + 8;
                    afr[nxt][f][0] = sA[row0 * 32 + sw0];
                    afr[nxt][f][1] = sA[row1 * 32 + sw0];
                    afr[nxt][f][2] = sA[row0 * 32 + sw1];
                    afr[nxt][f][3] = sA[row1 * 32 + sw1];
                }
#pragma unroll
                for (int j = 0; j < 8; ++j) {
                    const int n0 = wn * 64 + j * 8 + q;
                    bfr[nxt][j][0] = sB[n0 * 32 + sw0];
                    bfr[nxt][j][1] = sB[n0 * 32 + sw1];
                }
            }
#pragma unroll
            for (int f = 0; f < 4; ++f)
#pragma unroll
                for (int j = 0; j < 8; ++j)
                    mma_tf32(acc[f][j], afr[cur][f], bfr[cur][j]);
        }
    }

    // epilogue: add bias, store; optional per-row sum-of-squares accumulation
#pragma unroll
    for (int f = 0; f < 4; ++f) {
        const int row0 = bm + wm * 64 + f * 16 + q;
        float ss0 = 0.f, ss1 = 0.f;
#pragma unroll
        for (int j = 0; j < 8; ++j) {
            const int col = bn + wn * 64 + j * 8 + r * 2;
            const float b0 = __ldg(&bias[col]);
            const float b1 = __ldg(&bias[col + 1]);
            float2 v0 = make_float2(acc[f][j][0] + b0, acc[f][j][1] + b1);
            float2 v1 = make_float2(acc[f][j][2] + b0, acc[f][j][3] + b1);
            *(float2*)&C[(size_t)row0 * DIMC + col]       = v0;
            *(float2*)&C[(size_t)(row0 + 8) * DIMC + col] = v1;
            ss0 += v0.x * v0.x + v0.y * v0.y;
            ss1 += v1.x * v1.x + v1.y * v1.y;
        }
        if (ss) {
            ss0 += __shfl_xor_sync(0xffffffffu, ss0, 1);
            ss0 += __shfl_xor_sync(0xffffffffu, ss0, 2);
            ss1 += __shfl_xor_sync(0xffffffffu, ss1, 1);
            ss1 += __shfl_xor_sync(0xffffffffu, ss1, 2);
            if (r == 0) {
                atomicAdd(&ss[row0], ss0);
                atomicAdd(&ss[row0 + 8], ss1);
            }
        }
    }
}

// fused QKV: blockIdx.x in [0,12): matrix m = bx>>2, n-block = (bx&3)*256
__global__ __launch_bounds__(256)
void gemm_qkv_kernel(const float* __restrict__ A,
                     const float* __restrict__ Wbase,
                     const float* __restrict__ qb,
                     const float* __restrict__ kb,
                     const float* __restrict__ vb,
                     float* __restrict__ Cq,
                     float* __restrict__ Ck,
                     float* __restrict__ Cv,
                     float* __restrict__ ssq,
                     float* __restrict__ ssk)
{
    extern __shared__ char dsm[];
    const int m  = blockIdx.x >> 2;
    const int bn = (blockIdx.x & 3) * 256;
    const int bm = blockIdx.y * 128;

    const float* W    = Wbase + (size_t)m * (DIMC * DIMC);
    const float* bias = (m == 0) ? qb : (m == 1) ? kb : vb;
    float* C          = (m == 0) ? Cq : (m == 1) ? Ck : Cv;
    float* ss         = (m == 0) ? ssq : (m == 1) ? ssk : nullptr;

    gemm_body(A, W, bias, C, ss, bm, bn, dsm);
}

// single GEMM (output projection)
__global__ __launch_bounds__(256)
void gemm_tc_kernel(const float* __restrict__ A,
                    const float* __restrict__ W,
                    const float* __restrict__ bias,
                    float* __restrict__ C)
{
    extern __shared__ char dsm[];
    gemm_body(A, W, bias, C, nullptr,
              blockIdx.y * 128, blockIdx.x * 256, dsm);
}

// ---------------- zero the sum-of-squares accumulators ----------------------
__global__ void zero_ss_kernel(float* __restrict__ a, float* __restrict__ b)
{
    const int i = blockIdx.x * blockDim.x + threadIdx.x;
    if (i < TROWS) { a[i] = 0.f; b[i] = 0.f; }
}

// ---------------- windowed frame attention w/ fused rmsnorm+rope -----------
// One block (128 thr) per (si, head). 16 frames x 64 dims. Mask: j<=i, i-j<8.
// Output go is stored tf32-rounded (feeds the final GEMM raw-bit path).
__global__ __launch_bounds__(128)
void attn_kernel(const float* __restrict__ q,
                 const float* __restrict__ k,
                 const float* __restrict__ v,
                 float* __restrict__ o,
                 const float* __restrict__ ssq,
                 const float* __restrict__ ssk,
                 const float* __restrict__ nqw,
                 const float* __restrict__ nkw,
                 const float* __restrict__ fcos,
                 const float* __restrict__ fsin)
{
    const int si  = blockIdx.x;
    const int h   = blockIdx.y;
    const int tid = threadIdx.x;

    __shared__ float sq[16][68];   // padded rows: conflict-free column loads
    __shared__ float sk[16][68];
    __shared__ float sv[16][68];
    __shared__ float sS[16][17];
    __shared__ float scq[16], sck[16];
    __shared__ float swq[64], swk[64];

    if (tid < 16) {
        const int t = tid * SQ + si;
        scq[tid] = rsqrtf(ssq[t] * (1.0f / 1024.0f) + 1e-6f);
        sck[tid] = rsqrtf(ssk[t] * (1.0f / 1024.0f) + 1e-6f);
        *(float4*)&swq[tid * 4] = *(const float4*)&nqw[h * HDC + tid * 4];
        *(float4*)&swk[tid * 4] = *(const float4*)&nkw[h * HDC + tid * 4];
    }
    __syncthreads();

    // load q/k/v tiles; apply rmsnorm scale + rope to q,k on the fly
#pragma unroll
    for (int e = tid; e < 256; e += 128) {
        const int f  = e >> 4;
        const int d4 = (e & 15) * 4;
        const int t  = f * SQ + si;
        const size_t base = ((size_t)t) * DIMC + h * HDC + d4;

        const int m0 = d4 >> 1;        // rope pair indices within head
        const int m1 = m0 + 1;
        const float c0 = fcos[(size_t)t * 32 + m0];
        const float s0 = fsin[(size_t)t * 32 + m0];
        const float c1 = fcos[(size_t)t * 32 + m1];
        const float s1 = fsin[(size_t)t * 32 + m1];

        {
            const float4 qv = *(const float4*)&q[base];
            const float a = scq[f];
            const float h0 = qv.x * a * swq[d4 + 0];
            const float h1 = qv.y * a * swq[d4 + 1];
            const float h2 = qv.z * a * swq[d4 + 2];
            const float h3 = qv.w * a * swq[d4 + 3];
            sq[f][d4 + 0] = h0 * c0 - h1 * s0;
            sq[f][d4 + 1] = h0 * s0 + h1 * c0;
            sq[f][d4 + 2] = h2 * c1 - h3 * s1;
            sq[f][d4 + 3] = h2 * s1 + h3 * c1;
        }
        {
            const float4 kv = *(const float4*)&k[base];
            const float a = sck[f];
            const float h0 = kv.x * a * swk[d4 + 0];
            const float h1 = kv.y * a * swk[d4 + 1];
            const float h2 = kv.z * a * swk[d4 + 2];
            const float h3 = kv.w * a * swk[d4 + 3];
            sk[f][d4 + 0] = h0 * c0 - h1 * s0;
            sk[f][d4 + 1] = h0 * s0 + h1 * c0;
            sk[f][d4 + 2] = h2 * c1 - h3 * s1;
            sk[f][d4 + 3] = h2 * s1 + h3 * c1;
        }
        *(float4*)&sv[f][d4] = *(const float4*)&v[base];
    }
    __syncthreads();

    // scores: thread handles (i1, j) and (i1+8, j)
    {
        const int i1 = tid >> 4;       // 0..7
        const int i2 = i1 + 8;         // 8..15
        const int j  = tid & 15;
        float s1 = 0.f, s2 = 0.f;
#pragma unroll
        for (int d = 0; d < 64; d += 4) {
            const float4 kk = *(const float4*)&sk[j][d];
            const float4 q1 = *(const float4*)&sq[i1][d];
            const float4 q2 = *(const float4*)&sq[i2][d];
            s1 += q1.x * kk.x + q1.y * kk.y + q1.z * kk.z + q1.w * kk.w;
            s2 += q2.x * kk.x + q2.y * kk.y + q2.z * kk.z + q2.w * kk.w;
        }
        const bool m1 = (j <= i1) && (i1 - j) < WINDOW;
        const bool m2 = (j <= i2) && (i2 - j) < WINDOW;
        sS[i1][j] = m1 ? s1 * 0.125f : -1e30f;
        sS[i2][j] = m2 ? s2 * 0.125f : -1e30f;
    }
    __syncthreads();

    // softmax per row
    if (tid < 16) {
        const int i = tid;
        float m = -1e30f;
#pragma unroll
        for (int j = 0; j < 16; ++j) m = fmaxf(m, sS[i][j]);
        float e[16];
        float sum = 0.f;
#pragma unroll
        for (int j = 0; j < 16; ++j) { e[j] = expf(sS[i][j] - m); sum += e[j]; }
        const float inv = 1.f / sum;
#pragma unroll
        for (int j = 0; j < 16; ++j) sS[i][j] = e[j] * inv;
    }
    __syncthreads();

    // O = attn @ V : thread owns (i = tid>>3, 8 dims at d0=(tid&7)*8)
    // stored tf32-rounded for the final GEMM
    {
        const int i  = tid >> 3;        // 0..15
        const int d0 = (tid & 7) * 8;   // 0..56
        float4 a0 = make_float4(0.f, 0.f, 0.f, 0.f);
        float4 a1 = make_float4(0.f, 0.f, 0.f, 0.f);
#pragma unroll
        for (int j = 0; j < 16; ++j) {
            const float s  = sS[i][j];
            const float4 v0 = *(const float4*)&sv[j][d0];
            const float4 v1 = *(const float4*)&sv[j][d0 + 4];
            a0.x += s * v0.x; a0.y += s * v0.y; a0.z += s * v0.z; a0.w += s * v0.w;
            a1.x += s * v1.x; a1.y += s * v1.y; a1.z += s * v1.z; a1.w += s * v1.w;
        }
        a0.x = f2tf32f(a0.x); a0.y = f2tf32f(a0.y);
        a0.z = f2tf32f(a0.z); a0.w = f2tf32f(a0.w);
        a1.x = f2tf32f(a1.x); a1.y = f2tf32f(a1.y);
        a1.z = f2tf32f(a1.z); a1.w = f2tf32f(a1.w);
        float* orow = &o[((size_t)(i * SQ + si)) * DIMC + h * HDC + d0];
        *(float4*)&orow[0] = a0;
        *(float4*)&orow[4] = a1;
    }
}

// ---------------- launch ----------------------------------------------------
extern "C" void kernel_launch(void* const* d_in, const int* in_sizes, int n_in,
                              void* d_out, int out_size)
{
    const float* x   = (const float*)d_in[0];
    const float* fc  = (const float*)d_in[1];
    const float* fs  = (const float*)d_in[2];
    const float* q_w = (const float*)d_in[3];
    const float* q_b = (const float*)d_in[4];
    const float* k_w = (const float*)d_in[5];
    const float* k_b = (const float*)d_in[6];
    const float* v_w = (const float*)d_in[7];
    const float* v_b = (const float*)d_in[8];
    const float* o_w = (const float*)d_in[9];
    const float* o_b = (const float*)d_in[10];
    const float* nqw = (const float*)d_in[11];
    const float* nkw = (const float*)d_in[12];
    float* out = (float*)d_out;

    float *gq, *gk, *gv, *go, *gx, *gw, *gssq, *gssk;
    cudaGetSymbolAddress((void**)&gq, g_q);
    cudaGetSymbolAddress((void**)&gk, g_k);
    cudaGetSymbolAddress((void**)&gv, g_v);
    cudaGetSymbolAddress((void**)&go, g_o);
    cudaGetSymbolAddress((void**)&gx, g_x);
    cudaGetSymbolAddress((void**)&gw, g_w);
    cudaGetSymbolAddress((void**)&gssq, g_ssq);
    cudaGetSymbolAddress((void**)&gssk, g_ssk);

    float* gwo = gw + 3 * (size_t)(DIMC * DIMC);

    cudaFuncSetAttribute(gemm_qkv_kernel,
                         cudaFuncAttributeMaxDynamicSharedMemorySize, DSMEM_BYTES);
    cudaFuncSetAttribute(gemm_tc_kernel,
                         cudaFuncAttributeMaxDynamicSharedMemorySize, DSMEM_BYTES);

    // prepass: tf32-round x and the four weight matrices
    const int xw4 = (TROWS * DIMC) / 4;
    const int ww4 = (DIMC * DIMC) / 4;
    round_tf32_kernel<<<(xw4 + 255) / 256, 256>>>(x, gx, xw4);
    round_w_kernel<<<dim3((ww4 + 255) / 256, 4), 256>>>(q_w, k_w, v_w, o_w,
                                                        gw, ww4);
    zero_ss_kernel<<<(TROWS + 255) / 256, 256>>>(gssq, gssk);

    // fused Q,K,V projections: one launch, 12 n-blocks x 184 m-blocks
    gemm_qkv_kernel<<<dim3(12, TROWS / 128), 256, DSMEM_BYTES>>>(
        gx, gw, q_b, k_b, v_b, gq, gk, gv, gssq, gssk);

    attn_kernel<<<dim3(SQ, NHC), 128>>>(gq, gk, gv, go,
                                        gssq, gssk, nqw, nkw, fc, fs);

    gemm_tc_kernel<<<dim3(DIMC / 256, TROWS / 128), 256, DSMEM_BYTES>>>(
        go, gwo, o_b, out);
}

// round 14
// speedup vs baseline: 1.0630x; 1.0630x over previous
#include <cuda_runtime.h>
#include <cuda_bf16.h>
#include <cstdint>
#include <math.h>

// Problem constants (fixed by setup_inputs)
#define DIMC   1024
#define NHC    16
#define HDC    64
#define FQ     16          // frames
#define SQ     1472        // tokens per frame
#define TROWS  (FQ * SQ)   // 23552 total rows
#define WINDOW 8

// ---------------- scratch (device globals; no allocation allowed) ----------
__device__ float g_q[(size_t)TROWS * DIMC];
__device__ float g_k[(size_t)TROWS * DIMC];
__device__ float g_v[(size_t)TROWS * DIMC];
__device__ float g_o[(size_t)TROWS * DIMC];     // tf32-rounded attn output
__device__ float g_x[(size_t)TROWS * DIMC];     // tf32-rounded x
__device__ float g_w[4][DIMC * DIMC];           // tf32-rounded weights q,k,v,o
__device__ float g_ssq[TROWS];
__device__ float g_ssk[TROWS];

// =================== helpers ================================================
__device__ __forceinline__ uint32_t smem_u32(const void* p) {
    uint32_t a;
    asm("{ .reg .u64 t; cvta.to.shared.u64 t, %1; cvt.u32.u64 %0, t; }"
        : "=r"(a) : "l"(p));
    return a;
}

#define CP_ASYNC16(dst, src) \
    asm volatile("cp.async.cg.shared.global [%0], [%1], 16;" \
                 :: "r"(dst), "l"(src) : "memory")
#define CP_COMMIT() asm volatile("cp.async.commit_group;" ::: "memory")
#define CP_WAIT(n)  asm volatile("cp.async.wait_group %0;" :: "n"(n) : "memory")

__device__ __forceinline__ float f2tf32f(float x) {
    uint32_t u;
    asm("cvt.rna.tf32.f32 %0, %1;" : "=r"(u) : "f"(x));
    return __uint_as_float(u);
}

__device__ __forceinline__ void mma_tf32(float* c, const uint32_t* a,
                                         const uint32_t* b) {
    asm volatile(
        "mma.sync.aligned.m16n8k8.row.col.f32.tf32.tf32.f32 "
        "{%0,%1,%2,%3}, {%4,%5,%6,%7}, {%8,%9}, {%0,%1,%2,%3};"
        : "+f"(c[0]), "+f"(c[1]), "+f"(c[2]), "+f"(c[3])
        : "r"(a[0]), "r"(a[1]), "r"(a[2]), "r"(a[3]),
          "r"(b[0]), "r"(b[1]));
}

// ---------------- tf32 rounding prepasses -----------------------------------
__global__ __launch_bounds__(256)
void round_tf32_kernel(const float* __restrict__ in, float* __restrict__ out,
                       int n4)
{
    const int i = blockIdx.x * blockDim.x + threadIdx.x;
    if (i < n4) {
        float4 v = *(const float4*)&in[(size_t)i * 4];
        v.x = f2tf32f(v.x);
        v.y = f2tf32f(v.y);
        v.z = f2tf32f(v.z);
        v.w = f2tf32f(v.w);
        *(float4*)&out[(size_t)i * 4] = v;
    }
}

// batched: round the 4 weight matrices in one launch (blockIdx.y selects)
__global__ __launch_bounds__(256)
void round_w_kernel(const float* __restrict__ w0, const float* __restrict__ w1,
                    const float* __restrict__ w2, const float* __restrict__ w3,
                    float* __restrict__ out /* g_w base */, int n4)
{
    const int m = blockIdx.y;
    const float* in = (m == 0) ? w0 : (m == 1) ? w1 : (m == 2) ? w2 : w3;
    float* o = out + (size_t)m * (DIMC * DIMC);
    const int i = blockIdx.x * blockDim.x + threadIdx.x;
    if (i < n4) {
        float4 v = *(const float4*)&in[(size_t)i * 4];
        v.x = f2tf32f(v.x);
        v.y = f2tf32f(v.y);
        v.z = f2tf32f(v.z);
        v.w = f2tf32f(v.w);
        *(float4*)&o[(size_t)i * 4] = v;
    }
}

// =================== mma.sync TF32 GEMM core ================================
// C[128,128] block tile, BK=32, 2-stage cp.async pipeline, 128 threads,
// 4 warps (2x2) with 64x64 warp tiles, 3 CTAs/SM.
// Fragment reads per K-tile: A 16K*2 + B 16K*2 = 64KB = 512 crossbar cyc
// = HMMA floor (512 cyc) -> crossbar ceiling ~100% (vs 67% at 32x64).
// A-fragments loaded per-m-frag (4 regs, reused) to fit the 170-reg cap.
#define GSTAGES      2
#define KT           32
#define KITERS       (DIMC / KT)             // 32
#define A_TILE_BYTES 16384                   // 128 rows x 32 floats
#define B_TILE_BYTES 16384                   // 128 rows x 32 floats
#define STAGE_BYTES  (A_TILE_BYTES + B_TILE_BYTES)   // 32 KB
#define DSMEM_BYTES  (GSTAGES * STAGE_BYTES)         // 64 KB
#define A_TILE_WORDS (A_TILE_BYTES / 4)

__device__ __forceinline__
void gemm_body(const float* __restrict__ A,
               const float* __restrict__ W,
               const float* __restrict__ bias,
               float* __restrict__ C,
               float* __restrict__ ss,
               int bm, int bn, char* dsm)
{
    const uint32_t* su = (const uint32_t*)dsm;

    const int tid  = threadIdx.x;
    const int wid  = tid >> 5;
    const int lane = tid & 31;
    const int q    = lane >> 2;   // 0..7
    const int r    = lane & 3;    // 0..3
    const int wm   = wid & 1;     // warp m block (64 rows of 128)
    const int wn   = wid >> 1;    // warp n block (64 cols of 128)

    const uint32_t sbase = smem_u32(dsm);

    float acc[4][8][4];
#pragma unroll
    for (int f = 0; f < 4; ++f)
#pragma unroll
        for (int j = 0; j < 8; ++j)
#pragma unroll
            for (int c = 0; c < 4; ++c) acc[f][j][c] = 0.f;

    // stage loader: A tile 128x32 (1024 f4) + B tile 128x32 (1024 f4),
    // 128 threads: 8 A-chunks + 8 B-chunks each, swizzled 16B stores
    auto issue_stage = [&](int kt_idx, int buf) {
        const int k0 = kt_idx * KT;
        const uint32_t ab = sbase + buf * STAGE_BYTES;
        const uint32_t bb = ab + A_TILE_BYTES;
#pragma unroll
        for (int it = 0; it < 8; ++it) {
            const int e   = tid + it * 128;    // 0..1023
            const int row = e >> 3;
            const int g   = e & 7;
            const uint32_t off = (uint32_t)(row * 128 + ((g ^ (row & 7)) << 4));
            CP_ASYNC16(ab + off, &A[(size_t)(bm + row) * DIMC + k0 + g * 4]);
            CP_ASYNC16(bb + off, &W[(size_t)(bn + row) * DIMC + k0 + g * 4]);
        }
        CP_COMMIT();
    };

    issue_stage(0, 0);
    issue_stage(1, 1);

    for (int kt = 0; kt < KITERS; ++kt) {
        if (kt < KITERS - 1) { CP_WAIT(1); } else { CP_WAIT(0); }
        __syncthreads();

        const int buf = kt & 1;
        const uint32_t* sA = su + (size_t)buf * (STAGE_BYTES / 4);
        const uint32_t* sB = sA + A_TILE_WORDS;

#pragma unroll
        for (int ks = 0; ks < 4; ++ks) {
            const int g0 = ks * 2;
            const int sw0 = (g0 ^ q) * 4 + r;
            const int sw1 = ((g0 + 1) ^ q) * 4 + r;

            uint32_t b[8][2];
#pragma unroll
            for (int j = 0; j < 8; ++j) {
                const int n0 = wn * 64 + j * 8 + q;        // n%8 == q
                b[j][0] = sB[n0 * 32 + sw0];
                b[j][1] = sB[n0 * 32 + sw1];
            }
#pragma unroll
            for (int f = 0; f < 4; ++f) {
                uint32_t a[4];
                const int row0 = wm * 64 + f * 16 + q;     // row%8 == q
                const int row1 = row0 + 8;
                a[0] = sA[row0 * 32 + sw0];
                a[1] = sA[row1 * 32 + sw0];
                a[2] = sA[row0 * 32 + sw1];
                a[3] = sA[row1 * 32 + sw1];
#pragma unroll
                for (int j = 0; j < 8; ++j)
                    mma_tf32(acc[f][j], a, b[j]);
            }
        }

        __syncthreads();                 // all warps done reading buf
        if (kt + 2 < KITERS) issue_stage(kt + 2, buf);
    }

    // epilogue: add bias, store; optional per-row sum-of-squares accumulation
#pragma unroll
    for (int f = 0; f < 4; ++f) {
        const int row0 = bm + wm * 64 + f * 16 + q;
        float ss0 = 0.f, ss1 = 0.f;
#pragma unroll
        for (int j = 0; j < 8; ++j) {
            const int col = bn + wn * 64 + j * 8 + r * 2;
            const float b0 = __ldg(&bias[col]);
            const float b1 = __ldg(&bias[col + 1]);
            float2 v0 = make_float2(acc[f][j][0] + b0, acc[f][j][1] + b1);
            float2 v1 = make_float2(acc[f][j][2] + b0, acc[f][j][3] + b1);
            *(float2*)&C[(size_t)row0 * DIMC + col]       = v0;
            *(float2*)&C[(size_t)(row0 + 8) * DIMC + col] = v1;
            ss0 += v0.x * v0.x + v0.y * v0.y;
            ss1 += v1.x * v1.x + v1.y * v1.y;
        }
        if (ss) {
            ss0 += __shfl_xor_sync(0xffffffffu, ss0, 1);
            ss0 += __shfl_xor_sync(0xffffffffu, ss0, 2);
            ss1 += __shfl_xor_sync(0xffffffffu, ss1, 1);
            ss1 += __shfl_xor_sync(0xffffffffu, ss1, 2);
            if (r == 0) {
                atomicAdd(&ss[row0], ss0);
                atomicAdd(&ss[row0 + 8], ss1);
            }
        }
    }
}

// fused QKV: blockIdx.x in [0,24): matrix m = bx>>3, n-block = (bx&7)*128
__global__ __launch_bounds__(128, 3)
void gemm_qkv_kernel(const float* __restrict__ A,
                     const float* __restrict__ Wbase,
                     const float* __restrict__ qb,
                     const float* __restrict__ kb,
                     const float* __restrict__ vb,
                     float* __restrict__ Cq,
                     float* __restrict__ Ck,
                     float* __restrict__ Cv,
                     float* __restrict__ ssq,
                     float* __restrict__ ssk)
{
    extern __shared__ char dsm[];
    const int m  = blockIdx.x >> 3;
    const int bn = (blockIdx.x & 7) * 128;
    const int bm = blockIdx.y * 128;

    const float* W    = Wbase + (size_t)m * (DIMC * DIMC);
    const float* bias = (m == 0) ? qb : (m == 1) ? kb : vb;
    float* C          = (m == 0) ? Cq : (m == 1) ? Ck : Cv;
    float* ss         = (m == 0) ? ssq : (m == 1) ? ssk : nullptr;

    gemm_body(A, W, bias, C, ss, bm, bn, dsm);
}

// single GEMM (output projection)
__global__ __launch_bounds__(128, 3)
void gemm_tc_kernel(const float* __restrict__ A,
                    const float* __restrict__ W,
                    const float* __restrict__ bias,
                    float* __restrict__ C)
{
    extern __shared__ char dsm[];
    gemm_body(A, W, bias, C, nullptr,
              blockIdx.y * 128, blockIdx.x * 128, dsm);
}

// ---------------- zero the sum-of-squares accumulators ----------------------
__global__ void zero_ss_kernel(float* __restrict__ a, float* __restrict__ b)
{
    const int i = blockIdx.x * blockDim.x + threadIdx.x;
    if (i < TROWS) { a[i] = 0.f; b[i] = 0.f; }
}

// ---------------- windowed frame attention w/ fused rmsnorm+rope -----------
// One block (128 thr) per (si, head). 16 frames x 64 dims. Mask: j<=i, i-j<8.
// Output go is stored tf32-rounded (feeds the final GEMM raw-bit path).
__global__ __launch_bounds__(128)
void attn_kernel(const float* __restrict__ q,
                 const float* __restrict__ k,
                 const float* __restrict__ v,
                 float* __restrict__ o,
                 const float* __restrict__ ssq,
                 const float* __restrict__ ssk,
                 const float* __restrict__ nqw,
                 const float* __restrict__ nkw,
                 const float* __restrict__ fcos,
                 const float* __restrict__ fsin)
{
    const int si  = blockIdx.x;
    const int h   = blockIdx.y;
    const int tid = threadIdx.x;

    __shared__ float sq[16][68];   // padded rows: conflict-free column loads
    __shared__ float sk[16][68];
    __shared__ float sv[16][68];
    __shared__ float sS[16][17];
    __shared__ float scq[16], sck[16];
    __shared__ float swq[64], swk[64];

    if (tid < 16) {
        const int t = tid * SQ + si;
        scq[tid] = rsqrtf(ssq[t] * (1.0f / 1024.0f) + 1e-6f);
        sck[tid] = rsqrtf(ssk[t] * (1.0f / 1024.0f) + 1e-6f);
        *(float4*)&swq[tid * 4] = *(const float4*)&nqw[h * HDC + tid * 4];
        *(float4*)&swk[tid * 4] = *(const float4*)&nkw[h * HDC + tid * 4];
    }
    __syncthreads();

    // load q/k/v tiles; apply rmsnorm scale + rope to q,k on the fly
#pragma unroll
    for (int e = tid; e < 256; e += 128) {
        const int f  = e >> 4;
        const int d4 = (e & 15) * 4;
        const int t  = f * SQ + si;
        const size_t base = ((size_t)t) * DIMC + h * HDC + d4;

        const int m0 = d4 >> 1;        // rope pair indices within head
        const int m1 = m0 + 1;
        const float c0 = fcos[(size_t)t * 32 + m0];
        const float s0 = fsin[(size_t)t * 32 + m0];
        const float c1 = fcos[(size_t)t * 32 + m1];
        const float s1 = fsin[(size_t)t * 32 + m1];

        {
            const float4 qv = *(const float4*)&q[base];
            const float a = scq[f];
            const float h0 = qv.x * a * swq[d4 + 0];
            const float h1 = qv.y * a * swq[d4 + 1];
            const float h2 = qv.z * a * swq[d4 + 2];
            const float h3 = qv.w * a * swq[d4 + 3];
            sq[f][d4 + 0] = h0 * c0 - h1 * s0;
            sq[f][d4 + 1] = h0 * s0 + h1 * c0;
            sq[f][d4 + 2] = h2 * c1 - h3 * s1;
            sq[f][d4 + 3] = h2 * s1 + h3 * c1;
        }
        {
            const float4 kv = *(const float4*)&k[base];
            const float a = sck[f];
            const float h0 = kv.x * a * swk[d4 + 0];
            const float h1 = kv.y * a * swk[d4 + 1];
            const float h2 = kv.z * a * swk[d4 + 2];
            const float h3 = kv.w * a * swk[d4 + 3];
            sk[f][d4 + 0] = h0 * c0 - h1 * s0;
            sk[f][d4 + 1] = h0 * s0 + h1 * c0;
            sk[f][d4 + 2] = h2 * c1 - h3 * s1;
            sk[f][d4 + 3] = h2 * s1 + h3 * c1;
        }
        *(float4*)&sv[f][d4] = *(const float4*)&v[base];
    }
    __syncthreads();

    // scores: thread handles (i1, j) and (i1+8, j)
    {
        const int i1 = tid >> 4;       // 0..7
        const int i2 = i1 + 8;         // 8..15
        const int j  = tid & 15;
        float s1 = 0.f, s2 = 0.f;
#pragma unroll
        for (int d = 0; d < 64; d += 4) {
            const float4 kk = *(const float4*)&sk[j][d];
            const float4 q1 = *(const float4*)&sq[i1][d];
            const float4 q2 = *(const float4*)&sq[i2][d];
            s1 += q1.x * kk.x + q1.y * kk.y + q1.z * kk.z + q1.w * kk.w;
            s2 += q2.x * kk.x + q2.y * kk.y + q2.z * kk.z + q2.w * kk.w;
        }
        const bool m1 = (j <= i1) && (i1 - j) < WINDOW;
        const bool m2 = (j <= i2) && (i2 - j) < WINDOW;
        sS[i1][j] = m1 ? s1 * 0.125f : -1e30f;
        sS[i2][j] = m2 ? s2 * 0.125f : -1e30f;
    }
    __syncthreads();

    // softmax per row
    if (tid < 16) {
        const int i = tid;
        float m = -1e30f;
#pragma unroll
        for (int j = 0; j < 16; ++j) m = fmaxf(m, sS[i][j]);
        float e[16];
        float sum = 0.f;
#pragma unroll
        for (int j = 0; j < 16; ++j) { e[j] = expf(sS[i][j] - m); sum += e[j]; }
        const float inv = 1.f / sum;
#pragma unroll
        for (int j = 0; j < 16; ++j) sS[i][j] = e[j] * inv;
    }
    __syncthreads();

    // O = attn @ V : thread owns (i = tid>>3, 8 dims at d0=(tid&7)*8)
    // stored tf32-rounded for the final GEMM
    {
        const int i  = tid >> 3;        // 0..15
        const int d0 = (tid & 7) * 8;   // 0..56
        float4 a0 = make_float4(0.f, 0.f, 0.f, 0.f);
        float4 a1 = make_float4(0.f, 0.f, 0.f, 0.f);
#pragma unroll
        for (int j = 0; j < 16; ++j) {
            const float s  = sS[i][j];
            const float4 v0 = *(const float4*)&sv[j][d0];
            const float4 v1 = *(const float4*)&sv[j][d0 + 4];
            a0.x += s * v0.x; a0.y += s * v0.y; a0.z += s * v0.z; a0.w += s * v0.w;
            a1.x += s * v1.x; a1.y += s * v1.y; a1.z += s * v1.z; a1.w += s * v1.w;
        }
        a0.x = f2tf32f(a0.x); a0.y = f2tf32f(a0.y);
        a0.z = f2tf32f(a0.z); a0.w = f2tf32f(a0.w);
        a1.x = f2tf32f(a1.x); a1.y = f2tf32f(a1.y);
        a1.z = f2tf32f(a1.z); a1.w = f2tf32f(a1.w);
        float* orow = &o[((size_t)(i * SQ + si)) * DIMC + h * HDC + d0];
        *(float4*)&orow[0] = a0;
        *(float4*)&orow[4] = a1;
    }
}

// ---------------- launch ----------------------------------------------------
extern "C" void kernel_launch(void* const* d_in, const int* in_sizes, int n_in,
                              void* d_out, int out_size)
{
    const float* x   = (const float*)d_in[0];
    const float* fc  = (const float*)d_in[1];
    const float* fs  = (const float*)d_in[2];
    const float* q_w = (const float*)d_in[3];
    const float* q_b = (const float*)d_in[4];
    const float* k_w = (const float*)d_in[5];
    const float* k_b = (const float*)d_in[6];
    const float* v_w = (const float*)d_in[7];
    const float* v_b = (const float*)d_in[8];
    const float* o_w = (const float*)d_in[9];
    const float* o_b = (const float*)d_in[10];
    const float* nqw = (const float*)d_in[11];
    const float* nkw = (const float*)d_in[12];
    float* out = (float*)d_out;

    float *gq, *gk, *gv, *go, *gx, *gw, *gssq, *gssk;
    cudaGetSymbolAddress((void**)&gq, g_q);
    cudaGetSymbolAddress((void**)&gk, g_k);
    cudaGetSymbolAddress((void**)&gv, g_v);
    cudaGetSymbolAddress((void**)&go, g_o);
    cudaGetSymbolAddress((void**)&gx, g_x);
    cudaGetSymbolAddress((void**)&gw, g_w);
    cudaGetSymbolAddress((void**)&gssq, g_ssq);
    cudaGetSymbolAddress((void**)&gssk, g_ssk);

    float* gwo = gw + 3 * (size_t)(DIMC * DIMC);

    cudaFuncSetAttribute(gemm_qkv_kernel,
                         cudaFuncAttributeMaxDynamicSharedMemorySize, DSMEM_BYTES);
    cudaFuncSetAttribute(gemm_tc_kernel,
                         cudaFuncAttributeMaxDynamicSharedMemorySize, DSMEM_BYTES);

    // prepass: tf32-round x and the four weight matrices
    const int xw4 = (TROWS * DIMC) / 4;
    const int ww4 = (DIMC * DIMC) / 4;
    round_tf32_kernel<<<(xw4 + 255) / 256, 256>>>(x, gx, xw4);
    round_w_kernel<<<dim3((ww4 + 255) / 256, 4), 256>>>(q_w, k_w, v_w, o_w,
                                                        gw, ww4);
    zero_ss_kernel<<<(TROWS + 255) / 256, 256>>>(gssq, gssk);

    // fused Q,K,V projections: one launch, 24 n-blocks x 184 m-blocks
    gemm_qkv_kernel<<<dim3(24, TROWS / 128), 128, DSMEM_BYTES>>>(
        gx, gw, q_b, k_b, v_b, gq, gk, gv, gssq, gssk);

    attn_kernel<<<dim3(SQ, NHC), 128>>>(gq, gk, gv, go,
                                        gssq, gssk, nqw, nkw, fc, fs);

    gemm_tc_kernel<<<dim3(DIMC / 128, TROWS / 128), 128, DSMEM_BYTES>>>(
        go, gwo, o_b, out);
}

// round 15
// speedup vs baseline: 1.1412x; 1.0736x over previous
#include <cuda_runtime.h>
#include <cuda_bf16.h>
#include <cstdint>
#include <math.h>

// Problem constants (fixed by setup_inputs)
#define DIMC   1024
#define NHC    16
#define HDC    64
#define FQ     16          // frames
#define SQ     1472        // tokens per frame
#define TROWS  (FQ * SQ)   // 23552 total rows
#define WINDOW 8

// ---------------- scratch (device globals; no allocation allowed) ----------
__device__ float g_q[(size_t)TROWS * DIMC];
__device__ float g_k[(size_t)TROWS * DIMC];
__device__ float g_v[(size_t)TROWS * DIMC];
__device__ float g_o[(size_t)TROWS * DIMC];     // tf32-rounded attn output
__device__ float g_x[(size_t)TROWS * DIMC];     // tf32-rounded x
__device__ float g_w[4][DIMC * DIMC];           // tf32-rounded weights q,k,v,o
__device__ float g_ssq[TROWS];
__device__ float g_ssk[TROWS];

// =================== helpers ================================================
__device__ __forceinline__ uint32_t smem_u32(const void* p) {
    uint32_t a;
    asm("{ .reg .u64 t; cvta.to.shared.u64 t, %1; cvt.u32.u64 %0, t; }"
        : "=r"(a) : "l"(p));
    return a;
}

#define CP_ASYNC16(dst, src) \
    asm volatile("cp.async.cg.shared.global [%0], [%1], 16;" \
                 :: "r"(dst), "l"(src) : "memory")
#define CP_COMMIT() asm volatile("cp.async.commit_group;" ::: "memory")
#define CP_WAIT(n)  asm volatile("cp.async.wait_group %0;" :: "n"(n) : "memory")

__device__ __forceinline__ float f2tf32f(float x) {
    uint32_t u;
    asm("cvt.rna.tf32.f32 %0, %1;" : "=r"(u) : "f"(x));
    return __uint_as_float(u);
}

__device__ __forceinline__ void mma_tf32(float* c, const uint32_t* a,
                                         const uint32_t* b) {
    asm volatile(
        "mma.sync.aligned.m16n8k8.row.col.f32.tf32.tf32.f32 "
        "{%0,%1,%2,%3}, {%4,%5,%6,%7}, {%8,%9}, {%0,%1,%2,%3};"
        : "+f"(c[0]), "+f"(c[1]), "+f"(c[2]), "+f"(c[3])
        : "r"(a[0]), "r"(a[1]), "r"(a[2]), "r"(a[3]),
          "r"(b[0]), "r"(b[1]));
}

// ---------------- tf32 rounding prepasses -----------------------------------
__global__ __launch_bounds__(256)
void round_tf32_kernel(const float* __restrict__ in, float* __restrict__ out,
                       int n4)
{
    const int i = blockIdx.x * blockDim.x + threadIdx.x;
    if (i < n4) {
        float4 v = *(const float4*)&in[(size_t)i * 4];
        v.x = f2tf32f(v.x);
        v.y = f2tf32f(v.y);
        v.z = f2tf32f(v.z);
        v.w = f2tf32f(v.w);
        *(float4*)&out[(size_t)i * 4] = v;
    }
}

// batched: round the 4 weight matrices in one launch (blockIdx.y selects)
__global__ __launch_bounds__(256)
void round_w_kernel(const float* __restrict__ w0, const float* __restrict__ w1,
                    const float* __restrict__ w2, const float* __restrict__ w3,
                    float* __restrict__ out /* g_w base */, int n4)
{
    const int m = blockIdx.y;
    const float* in = (m == 0) ? w0 : (m == 1) ? w1 : (m == 2) ? w2 : w3;
    float* o = out + (size_t)m * (DIMC * DIMC);
    const int i = blockIdx.x * blockDim.x + threadIdx.x;
    if (i < n4) {
        float4 v = *(const float4*)&in[(size_t)i * 4];
        v.x = f2tf32f(v.x);
        v.y = f2tf32f(v.y);
        v.z = f2tf32f(v.z);
        v.w = f2tf32f(v.w);
        *(float4*)&o[(size_t)i * 4] = v;
    }
}

// =================== mma.sync TF32 GEMM core ================================
// C[128,128] block tile, BK=32, 3-stage cp.async pipeline (distance 2,
// single barrier per K-tile — the R12-proven loop), 128 threads,
// 4 warps (2x2) with 64x64 warp tiles, 2 CTAs/SM.
// Fragment bytes: A 16K*2 + B 16K*2 = 64KB per 512K MAC = 0.125 B/MAC
// = crossbar floor -> ceiling ~100% (R12's 32x64 shape: 0.1875 -> 67%).
// Fragments register-double-buffered across k-steps (32-deep HMMA chains).
#define GSTAGES      3
#define KT           32
#define KITERS       (DIMC / KT)             // 32
#define A_TILE_BYTES 16384                   // 128 rows x 32 floats
#define B_TILE_BYTES 16384                   // 128 rows x 32 floats
#define STAGE_BYTES  (A_TILE_BYTES + B_TILE_BYTES)   // 32 KB
#define DSMEM_BYTES  (GSTAGES * STAGE_BYTES)         // 96 KB
#define A_TILE_WORDS (A_TILE_BYTES / 4)

__device__ __forceinline__
void gemm_body(const float* __restrict__ A,
               const float* __restrict__ W,
               const float* __restrict__ bias,
               float* __restrict__ C,
               float* __restrict__ ss,
               int bm, int bn, char* dsm)
{
    const uint32_t* su = (const uint32_t*)dsm;

    const int tid  = threadIdx.x;
    const int wid  = tid >> 5;
    const int lane = tid & 31;
    const int q    = lane >> 2;   // 0..7
    const int r    = lane & 3;    // 0..3
    const int wm   = wid & 1;     // warp m block (64 rows of 128)
    const int wn   = wid >> 1;    // warp n block (64 cols of 128)

    const uint32_t sbase = smem_u32(dsm);

    float acc[4][8][4];
#pragma unroll
    for (int f = 0; f < 4; ++f)
#pragma unroll
        for (int j = 0; j < 8; ++j)
#pragma unroll
            for (int c = 0; c < 4; ++c) acc[f][j][c] = 0.f;

    // stage loader: A tile 128x32 (1024 f4) + B tile 128x32 (1024 f4),
    // 128 threads: 8 A-chunks + 8 B-chunks each, swizzled 16B stores
    auto issue_stage = [&](int kt_idx, int buf) {
        const int k0 = kt_idx * KT;
        const uint32_t ab = sbase + buf * STAGE_BYTES;
        const uint32_t bb = ab + A_TILE_BYTES;
#pragma unroll
        for (int it = 0; it < 8; ++it) {
            const int e   = tid + it * 128;    // 0..1023
            const int row = e >> 3;
            const int g   = e & 7;
            const uint32_t off = (uint32_t)(row * 128 + ((g ^ (row & 7)) << 4));
            CP_ASYNC16(ab + off, &A[(size_t)(bm + row) * DIMC + k0 + g * 4]);
            CP_ASYNC16(bb + off, &W[(size_t)(bn + row) * DIMC + k0 + g * 4]);
        }
        CP_COMMIT();
    };

    issue_stage(0, 0);
    issue_stage(1, 1);

    uint32_t afr[2][4][4];
    uint32_t bfr[2][8][2];

    int buf_c = 0;   // buffer of current kt
    int buf_p = 2;   // buffer for kt+2
    for (int kt = 0; kt < KITERS; ++kt) {
        if (kt < KITERS - 1) { CP_WAIT(1); } else { CP_WAIT(0); }
        __syncthreads();
        if (kt + 2 < KITERS) issue_stage(kt + 2, buf_p);

        const uint32_t* sA = su + (size_t)buf_c * (STAGE_BYTES / 4);
        const uint32_t* sB = sA + A_TILE_WORDS;

        // prime: fragments for ks=0 into slot 0
        {
            const int sw0 = (0 ^ q) * 4 + r;
            const int sw1 = (1 ^ q) * 4 + r;
#pragma unroll
            for (int f = 0; f < 4; ++f) {
                const int row0 = wm * 64 + f * 16 + q;     // row%8 == q
                const int row1 = row0 + 8;
                afr[0][f][0] = sA[row0 * 32 + sw0];
                afr[0][f][1] = sA[row1 * 32 + sw0];
                afr[0][f][2] = sA[row0 * 32 + sw1];
                afr[0][f][3] = sA[row1 * 32 + sw1];
            }
#pragma unroll
            for (int j = 0; j < 8; ++j) {
                const int n0 = wn * 64 + j * 8 + q;        // n%8 == q
                bfr[0][j][0] = sB[n0 * 32 + sw0];
                bfr[0][j][1] = sB[n0 * 32 + sw1];
            }
        }

#pragma unroll
        for (int ks = 0; ks < 4; ++ks) {
            const int cur = ks & 1;
            const int nxt = cur ^ 1;
            if (ks < 3) {
                const int g0  = 2 * (ks + 1);
                const int sw0 = (g0 ^ q) * 4 + r;
                const int sw1 = ((g0 + 1) ^ q) * 4 + r;
#pragma unroll
                for (int f = 0; f < 4; ++f) {
                    const int row0 = wm * 64 + f * 16 + q;
                    const int row1 = row0 + 8;
                    afr[nxt][f][0] = sA[row0 * 32 + sw0];
                    afr[nxt][f][1] = sA[row1 * 32 + sw0];
                    afr[nxt][f][2] = sA[row0 * 32 + sw1];
                    afr[nxt][f][3] = sA[row1 * 32 + sw1];
                }
#pragma unroll
                for (int j = 0; j < 8; ++j) {
                    const int n0 = wn * 64 + j * 8 + q;
                    bfr[nxt][j][0] = sB[n0 * 32 + sw0];
                    bfr[nxt][j][1] = sB[n0 * 32 + sw1];
                }
            }
#pragma unroll
            for (int f = 0; f < 4; ++f)
#pragma unroll
                for (int j = 0; j < 8; ++j)
                    mma_tf32(acc[f][j], afr[cur][f], bfr[cur][j]);
        }

        buf_c = (buf_c == 2) ? 0 : buf_c + 1;
        buf_p = (buf_p == 2) ? 0 : buf_p + 1;
    }

    // epilogue: add bias, store; optional per-row sum-of-squares accumulation
#pragma unroll
    for (int f = 0; f < 4; ++f) {
        const int row0 = bm + wm * 64 + f * 16 + q;
        float ss0 = 0.f, ss1 = 0.f;
#pragma unroll
        for (int j = 0; j < 8; ++j) {
            const int col = bn + wn * 64 + j * 8 + r * 2;
            const float b0 = __ldg(&bias[col]);
            const float b1 = __ldg(&bias[col + 1]);
            float2 v0 = make_float2(acc[f][j][0] + b0, acc[f][j][1] + b1);
            float2 v1 = make_float2(acc[f][j][2] + b0, acc[f][j][3] + b1);
            *(float2*)&C[(size_t)row0 * DIMC + col]       = v0;
            *(float2*)&C[(size_t)(row0 + 8) * DIMC + col] = v1;
            ss0 += v0.x * v0.x + v0.y * v0.y;
            ss1 += v1.x * v1.x + v1.y * v1.y;
        }
        if (ss) {
            ss0 += __shfl_xor_sync(0xffffffffu, ss0, 1);
            ss0 += __shfl_xor_sync(0xffffffffu, ss0, 2);
            ss1 += __shfl_xor_sync(0xffffffffu, ss1, 1);
            ss1 += __shfl_xor_sync(0xffffffffu, ss1, 2);
            if (r == 0) {
                atomicAdd(&ss[row0], ss0);
                atomicAdd(&ss[row0 + 8], ss1);
            }
        }
    }
}

// fused QKV: blockIdx.x in [0,24): matrix m = bx>>3, n-block = (bx&7)*128
__global__ __launch_bounds__(128, 2)
void gemm_qkv_kernel(const float* __restrict__ A,
                     const float* __restrict__ Wbase,
                     const float* __restrict__ qb,
                     const float* __restrict__ kb,
                     const float* __restrict__ vb,
                     float* __restrict__ Cq,
                     float* __restrict__ Ck,
                     float* __restrict__ Cv,
                     float* __restrict__ ssq,
                     float* __restrict__ ssk)
{
    extern __shared__ char dsm[];
    const int m  = blockIdx.x >> 3;
    const int bn = (blockIdx.x & 7) * 128;
    const int bm = blockIdx.y * 128;

    const float* W    = Wbase + (size_t)m * (DIMC * DIMC);
    const float* bias = (m == 0) ? qb : (m == 1) ? kb : vb;
    float* C          = (m == 0) ? Cq : (m == 1) ? Ck : Cv;
    float* ss         = (m == 0) ? ssq : (m == 1) ? ssk : nullptr;

    gemm_body(A, W, bias, C, ss, bm, bn, dsm);
}

// single GEMM (output projection)
__global__ __launch_bounds__(128, 2)
void gemm_tc_kernel(const float* __restrict__ A,
                    const float* __restrict__ W,
                    const float* __restrict__ bias,
                    float* __restrict__ C)
{
    extern __shared__ char dsm[];
    gemm_body(A, W, bias, C, nullptr,
              blockIdx.y * 128, blockIdx.x * 128, dsm);
}

// ---------------- zero the sum-of-squares accumulators ----------------------
__global__ void zero_ss_kernel(float* __restrict__ a, float* __restrict__ b)
{
    const int i = blockIdx.x * blockDim.x + threadIdx.x;
    if (i < TROWS) { a[i] = 0.f; b[i] = 0.f; }
}

// ---------------- windowed frame attention w/ fused rmsnorm+rope -----------
// One block (128 thr) per (si, head). 16 frames x 64 dims. Mask: j<=i, i-j<8.
// Output go is stored tf32-rounded (feeds the final GEMM raw-bit path).
__global__ __launch_bounds__(128)
void attn_kernel(const float* __restrict__ q,
                 const float* __restrict__ k,
                 const float* __restrict__ v,
                 float* __restrict__ o,
                 const float* __restrict__ ssq,
                 const float* __restrict__ ssk,
                 const float* __restrict__ nqw,
                 const float* __restrict__ nkw,
                 const float* __restrict__ fcos,
                 const float* __restrict__ fsin)
{
    const int si  = blockIdx.x;
    const int h   = blockIdx.y;
    const int tid = threadIdx.x;

    __shared__ float sq[16][68];   // padded rows: conflict-free column loads
    __shared__ float sk[16][68];
    __shared__ float sv[16][68];
    __shared__ float sS[16][17];
    __shared__ float scq[16], sck[16];
    __shared__ float swq[64], swk[64];

    if (tid < 16) {
        const int t = tid * SQ + si;
        scq[tid] = rsqrtf(ssq[t] * (1.0f / 1024.0f) + 1e-6f);
        sck[tid] = rsqrtf(ssk[t] * (1.0f / 1024.0f) + 1e-6f);
        *(float4*)&swq[tid * 4] = *(const float4*)&nqw[h * HDC + tid * 4];
        *(float4*)&swk[tid * 4] = *(const float4*)&nkw[h * HDC + tid * 4];
    }
    __syncthreads();

    // load q/k/v tiles; apply rmsnorm scale + rope to q,k on the fly
#pragma unroll
    for (int e = tid; e < 256; e += 128) {
        const int f  = e >> 4;
        const int d4 = (e & 15) * 4;
        const int t  = f * SQ + si;
        const size_t base = ((size_t)t) * DIMC + h * HDC + d4;

        const int m0 = d4 >> 1;        // rope pair indices within head
        const int m1 = m0 + 1;
        const float c0 = fcos[(size_t)t * 32 + m0];
        const float s0 = fsin[(size_t)t * 32 + m0];
        const float c1 = fcos[(size_t)t * 32 + m1];
        const float s1 = fsin[(size_t)t * 32 + m1];

        {
            const float4 qv = *(const float4*)&q[base];
            const float a = scq[f];
            const float h0 = qv.x * a * swq[d4 + 0];
            const float h1 = qv.y * a * swq[d4 + 1];
            const float h2 = qv.z * a * swq[d4 + 2];
            const float h3 = qv.w * a * swq[d4 + 3];
            sq[f][d4 + 0] = h0 * c0 - h1 * s0;
            sq[f][d4 + 1] = h0 * s0 + h1 * c0;
            sq[f][d4 + 2] = h2 * c1 - h3 * s1;
            sq[f][d4 + 3] = h2 * s1 + h3 * c1;
        }
        {
            const float4 kv = *(const float4*)&k[base];
            const float a = sck[f];
            const float h0 = kv.x * a * swk[d4 + 0];
            const float h1 = kv.y * a * swk[d4 + 1];
            const float h2 = kv.z * a * swk[d4 + 2];
            const float h3 = kv.w * a * swk[d4 + 3];
            sk[f][d4 + 0] = h0 * c0 - h1 * s0;
            sk[f][d4 + 1] = h0 * s0 + h1 * c0;
            sk[f][d4 + 2] = h2 * c1 - h3 * s1;
            sk[f][d4 + 3] = h2 * s1 + h3 * c1;
        }
        *(float4*)&sv[f][d4] = *(const float4*)&v[base];
    }
    __syncthreads();

    // scores: thread handles (i1, j) and (i1+8, j)
    {
        const int i1 = tid >> 4;       // 0..7
        const int i2 = i1 + 8;         // 8..15
        const int j  = tid & 15;
        float s1 = 0.f, s2 = 0.f;
#pragma unroll
        for (int d = 0; d < 64; d += 4) {
            const float4 kk = *(const float4*)&sk[j][d];
            const float4 q1 = *(const float4*)&sq[i1][d];
            const float4 q2 = *(const float4*)&sq[i2][d];
            s1 += q1.x * kk.x + q1.y * kk.y + q1.z * kk.z + q1.w * kk.w;
            s2 += q2.x * kk.x + q2.y * kk.y + q2.z * kk.z + q2.w * kk.w;
        }
        const bool m1 = (j <= i1) && (i1 - j) < WINDOW;
        const bool m2 = (j <= i2) && (i2 - j) < WINDOW;
        sS[i1][j] = m1 ? s1 * 0.125f : -1e30f;
        sS[i2][j] = m2 ? s2 * 0.125f : -1e30f;
    }
    __syncthreads();

    // softmax per row
    if (tid < 16) {
        const int i = tid;
        float m = -1e30f;
#pragma unroll
        for (int j = 0; j < 16; ++j) m = fmaxf(m, sS[i][j]);
        float e[16];
        float sum = 0.f;
#pragma unroll
        for (int j = 0; j < 16; ++j) { e[j] = expf(sS[i][j] - m); sum += e[j]; }
        const float inv = 1.f / sum;
#pragma unroll
        for (int j = 0; j < 16; ++j) sS[i][j] = e[j] * inv;
    }
    __syncthreads();

    // O = attn @ V : thread owns (i = tid>>3, 8 dims at d0=(tid&7)*8)
    // stored tf32-rounded for the final GEMM
    {
        const int i  = tid >> 3;        // 0..15
        const int d0 = (tid & 7) * 8;   // 0..56
        float4 a0 = make_float4(0.f, 0.f, 0.f, 0.f);
        float4 a1 = make_float4(0.f, 0.f, 0.f, 0.f);
#pragma unroll
        for (int j = 0; j < 16; ++j) {
            const float s  = sS[i][j];
            const float4 v0 = *(const float4*)&sv[j][d0];
            const float4 v1 = *(const float4*)&sv[j][d0 + 4];
            a0.x += s * v0.x; a0.y += s * v0.y; a0.z += s * v0.z; a0.w += s * v0.w;
            a1.x += s * v1.x; a1.y += s * v1.y; a1.z += s * v1.z; a1.w += s * v1.w;
        }
        a0.x = f2tf32f(a0.x); a0.y = f2tf32f(a0.y);
        a0.z = f2tf32f(a0.z); a0.w = f2tf32f(a0.w);
        a1.x = f2tf32f(a1.x); a1.y = f2tf32f(a1.y);
        a1.z = f2tf32f(a1.z); a1.w = f2tf32f(a1.w);
        float* orow = &o[((size_t)(i * SQ + si)) * DIMC + h * HDC + d0];
        *(float4*)&orow[0] = a0;
        *(float4*)&orow[4] = a1;
    }
}

// ---------------- launch ----------------------------------------------------
extern "C" void kernel_launch(void* const* d_in, const int* in_sizes, int n_in,
                              void* d_out, int out_size)
{
    const float* x   = (const float*)d_in[0];
    const float* fc  = (const float*)d_in[1];
    const float* fs  = (const float*)d_in[2];
    const float* q_w = (const float*)d_in[3];
    const float* q_b = (const float*)d_in[4];
    const float* k_w = (const float*)d_in[5];
    const float* k_b = (const float*)d_in[6];
    const float* v_w = (const float*)d_in[7];
    const float* v_b = (const float*)d_in[8];
    const float* o_w = (const float*)d_in[9];
    const float* o_b = (const float*)d_in[10];
    const float* nqw = (const float*)d_in[11];
    const float* nkw = (const float*)d_in[12];
    float* out = (float*)d_out;

    float *gq, *gk, *gv, *go, *gx, *gw, *gssq, *gssk;
    cudaGetSymbolAddress((void**)&gq, g_q);
    cudaGetSymbolAddress((void**)&gk, g_k);
    cudaGetSymbolAddress((void**)&gv, g_v);
    cudaGetSymbolAddress((void**)&go, g_o);
    cudaGetSymbolAddress((void**)&gx, g_x);
    cudaGetSymbolAddress((void**)&gw, g_w);
    cudaGetSymbolAddress((void**)&gssq, g_ssq);
    cudaGetSymbolAddress((void**)&gssk, g_ssk);

    float* gwo = gw + 3 * (size_t)(DIMC * DIMC);

    cudaFuncSetAttribute(gemm_qkv_kernel,
                         cudaFuncAttributeMaxDynamicSharedMemorySize, DSMEM_BYTES);
    cudaFuncSetAttribute(gemm_tc_kernel,
                         cudaFuncAttributeMaxDynamicSharedMemorySize, DSMEM_BYTES);

    // prepass: tf32-round x and the four weight matrices
    const int xw4 = (TROWS * DIMC) / 4;
    const int ww4 = (DIMC * DIMC) / 4;
    round_tf32_kernel<<<(xw4 + 255) / 256, 256>>>(x, gx, xw4);
    round_w_kernel<<<dim3((ww4 + 255) / 256, 4), 256>>>(q_w, k_w, v_w, o_w,
                                                        gw, ww4);
    zero_ss_kernel<<<(TROWS + 255) / 256, 256>>>(gssq, gssk);

    // fused Q,K,V projections: one launch, 24 n-blocks x 184 m-blocks
    gemm_qkv_kernel<<<dim3(24, TROWS / 128), 128, DSMEM_BYTES>>>(
        gx, gw, q_b, k_b, v_b, gq, gk, gv, gssq, gssk);

    attn_kernel<<<dim3(SQ, NHC), 128>>>(gq, gk, gv, go,
                                        gssq, gssk, nqw, nkw, fc, fs);

    gemm_tc_kernel<<<dim3(DIMC / 128, TROWS / 128), 128, DSMEM_BYTES>>>(
        go, gwo, o_b, out);
}

// round 16
// speedup vs baseline: 1.1512x; 1.0087x over previous
#include <cuda_runtime.h>
#include <cuda_bf16.h>
#include <cstdint>
#include <math.h>

// Problem constants (fixed by setup_inputs)
#define DIMC   1024
#define NHC    16
#define HDC    64
#define FQ     16          // frames
#define SQ     1472        // tokens per frame
#define TROWS  (FQ * SQ)   // 23552 total rows
#define WINDOW 8

// ---------------- scratch (device globals; no allocation allowed) ----------
__device__ float g_q[(size_t)TROWS * DIMC];
__device__ float g_k[(size_t)TROWS * DIMC];
__device__ float g_v[(size_t)TROWS * DIMC];
__device__ float g_o[(size_t)TROWS * DIMC];     // tf32-rounded attn output
__device__ float g_x[(size_t)TROWS * DIMC];     // tf32-rounded x
__device__ float g_w[4][DIMC * DIMC];           // tf32-rounded weights q,k,v,o
__device__ float g_ssq[TROWS];
__device__ float g_ssk[TROWS];

// =================== helpers ================================================
__device__ __forceinline__ uint32_t smem_u32(const void* p) {
    uint32_t a;
    asm("{ .reg .u64 t; cvta.to.shared.u64 t, %1; cvt.u32.u64 %0, t; }"
        : "=r"(a) : "l"(p));
    return a;
}

#define CP_ASYNC16(dst, src) \
    asm volatile("cp.async.cg.shared.global [%0], [%1], 16;" \
                 :: "r"(dst), "l"(src) : "memory")
#define CP_COMMIT() asm volatile("cp.async.commit_group;" ::: "memory")
#define CP_WAIT(n)  asm volatile("cp.async.wait_group %0;" :: "n"(n) : "memory")

__device__ __forceinline__ float f2tf32f(float x) {
    uint32_t u;
    asm("cvt.rna.tf32.f32 %0, %1;" : "=r"(u) : "f"(x));
    return __uint_as_float(u);
}

__device__ __forceinline__ void mma_tf32(float* c, const uint32_t* a,
                                         const uint32_t* b) {
    asm volatile(
        "mma.sync.aligned.m16n8k8.row.col.f32.tf32.tf32.f32 "
        "{%0,%1,%2,%3}, {%4,%5,%6,%7}, {%8,%9}, {%0,%1,%2,%3};"
        : "+f"(c[0]), "+f"(c[1]), "+f"(c[2]), "+f"(c[3])
        : "r"(a[0]), "r"(a[1]), "r"(a[2]), "r"(a[3]),
          "r"(b[0]), "r"(b[1]));
}

// ---------------- tf32 rounding prepasses -----------------------------------
__global__ __launch_bounds__(256)
void round_tf32_kernel(const float* __restrict__ in, float* __restrict__ out,
                       int n4)
{
    const int i = blockIdx.x * blockDim.x + threadIdx.x;
    if (i < n4) {
        float4 v = *(const float4*)&in[(size_t)i * 4];
        v.x = f2tf32f(v.x);
        v.y = f2tf32f(v.y);
        v.z = f2tf32f(v.z);
        v.w = f2tf32f(v.w);
        *(float4*)&out[(size_t)i * 4] = v;
    }
}

// batched: round the 4 weight matrices in one launch (blockIdx.y selects)
__global__ __launch_bounds__(256)
void round_w_kernel(const float* __restrict__ w0, const float* __restrict__ w1,
                    const float* __restrict__ w2, const float* __restrict__ w3,
                    float* __restrict__ out /* g_w base */, int n4)
{
    const int m = blockIdx.y;
    const float* in = (m == 0) ? w0 : (m == 1) ? w1 : (m == 2) ? w2 : w3;
    float* o = out + (size_t)m * (DIMC * DIMC);
    const int i = blockIdx.x * blockDim.x + threadIdx.x;
    if (i < n4) {
        float4 v = *(const float4*)&in[(size_t)i * 4];
        v.x = f2tf32f(v.x);
        v.y = f2tf32f(v.y);
        v.z = f2tf32f(v.z);
        v.w = f2tf32f(v.w);
        *(float4*)&o[(size_t)i * 4] = v;
    }
}

// =================== mma.sync TF32 GEMM core ================================
// C[128,128] block tile, BK=32, 3-stage cp.async pipeline (distance 2,
// single barrier per K-tile), 128 threads, 4 warps (2x2) with 64x64 warp
// tiles, 2 CTAs/SM. Fragments register-double-buffered across k-steps AND
// across K-tiles: during ks=3 of tile kt, the ks=0 fragments of tile kt+1
// are loaded from the already-complete next buffer (no post-barrier LDS
// latency exposure).
#define GSTAGES      3
#define KT           32
#define KITERS       (DIMC / KT)             // 32
#define A_TILE_BYTES 16384                   // 128 rows x 32 floats
#define B_TILE_BYTES 16384                   // 128 rows x 32 floats
#define STAGE_BYTES  (A_TILE_BYTES + B_TILE_BYTES)   // 32 KB
#define DSMEM_BYTES  (GSTAGES * STAGE_BYTES)         // 96 KB
#define A_TILE_WORDS (A_TILE_BYTES / 4)

__device__ __forceinline__
void gemm_body(const float* __restrict__ A,
               const float* __restrict__ W,
               const float* __restrict__ bias,
               float* __restrict__ C,
               float* __restrict__ ss,
               int bm, int bn, char* dsm)
{
    const uint32_t* su = (const uint32_t*)dsm;

    const int tid  = threadIdx.x;
    const int wid  = tid >> 5;
    const int lane = tid & 31;
    const int q    = lane >> 2;   // 0..7
    const int r    = lane & 3;    // 0..3
    const int wm   = wid & 1;     // warp m block (64 rows of 128)
    const int wn   = wid >> 1;    // warp n block (64 cols of 128)

    const uint32_t sbase = smem_u32(dsm);

    float acc[4][8][4];
#pragma unroll
    for (int f = 0; f < 4; ++f)
#pragma unroll
        for (int j = 0; j < 8; ++j)
#pragma unroll
            for (int c = 0; c < 4; ++c) acc[f][j][c] = 0.f;

    // stage loader: A tile 128x32 (1024 f4) + B tile 128x32 (1024 f4),
    // 128 threads: 8 A-chunks + 8 B-chunks each, swizzled 16B stores
    auto issue_stage = [&](int kt_idx, int buf) {
        const int k0 = kt_idx * KT;
        const uint32_t ab = sbase + buf * STAGE_BYTES;
        const uint32_t bb = ab + A_TILE_BYTES;
#pragma unroll
        for (int it = 0; it < 8; ++it) {
            const int e   = tid + it * 128;    // 0..1023
            const int row = e >> 3;
            const int g   = e & 7;
            const uint32_t off = (uint32_t)(row * 128 + ((g ^ (row & 7)) << 4));
            CP_ASYNC16(ab + off, &A[(size_t)(bm + row) * DIMC + k0 + g * 4]);
            CP_ASYNC16(bb + off, &W[(size_t)(bn + row) * DIMC + k0 + g * 4]);
        }
        CP_COMMIT();
    };

    issue_stage(0, 0);
    issue_stage(1, 1);

    uint32_t afr[2][4][4];
    uint32_t bfr[2][8][2];

    // fragment loader into slot s from tile buffers (sA/sB), k-group pair g0
    auto load_frags = [&](uint32_t (*af)[4], uint32_t (*bf)[2],
                          const uint32_t* sA, const uint32_t* sB, int g0) {
        const int sw0 = (g0 ^ q) * 4 + r;
        const int sw1 = ((g0 + 1) ^ q) * 4 + r;
#pragma unroll
        for (int f = 0; f < 4; ++f) {
            const int row0 = wm * 64 + f * 16 + q;     // row%8 == q
            const int row1 = row0 + 8;
            af[f][0] = sA[row0 * 32 + sw0];
            af[f][1] = sA[row1 * 32 + sw0];
            af[f][2] = sA[row0 * 32 + sw1];
            af[f][3] = sA[row1 * 32 + sw1];
        }
#pragma unroll
        for (int j = 0; j < 8; ++j) {
            const int n0 = wn * 64 + j * 8 + q;        // n%8 == q
            bf[j][0] = sB[n0 * 32 + sw0];
            bf[j][1] = sB[n0 * 32 + sw1];
        }
    };

    int buf_c = 0;   // buffer of current kt
    int buf_p = 2;   // buffer for kt+2
    for (int kt = 0; kt < KITERS; ++kt) {
        if (kt < KITERS - 1) { CP_WAIT(1); } else { CP_WAIT(0); }
        __syncthreads();
        if (kt + 2 < KITERS) issue_stage(kt + 2, buf_p);

        const uint32_t* sA = su + (size_t)buf_c * (STAGE_BYTES / 4);
        const uint32_t* sB = sA + A_TILE_WORDS;

        // prime only for the very first tile; afterwards ks=0 fragments
        // were preloaded during ks=3 of the previous tile
        if (kt == 0)
            load_frags(afr[0], bfr[0], sA, sB, 0);

#pragma unroll
        for (int ks = 0; ks < 4; ++ks) {
            const int cur = ks & 1;
            const int nxt = cur ^ 1;
            if (ks < 3) {
                load_frags(afr[nxt], bfr[nxt], sA, sB, 2 * (ks + 1));
            } else if (kt + 1 < KITERS) {
                // next tile's buffer (distance-2 pipeline: already complete)
                const int buf_n = (buf_c == 2) ? 0 : buf_c + 1;
                const uint32_t* sAn = su + (size_t)buf_n * (STAGE_BYTES / 4);
                const uint32_t* sBn = sAn + A_TILE_WORDS;
                load_frags(afr[nxt], bfr[nxt], sAn, sBn, 0);
            }
#pragma unroll
            for (int f = 0; f < 4; ++f)
#pragma unroll
                for (int j = 0; j < 8; ++j)
                    mma_tf32(acc[f][j], afr[cur][f], bfr[cur][j]);
        }

        buf_c = (buf_c == 2) ? 0 : buf_c + 1;
        buf_p = (buf_p == 2) ? 0 : buf_p + 1;
    }

    // epilogue: add bias, store; optional per-row sum-of-squares accumulation
#pragma unroll
    for (int f = 0; f < 4; ++f) {
        const int row0 = bm + wm * 64 + f * 16 + q;
        float ss0 = 0.f, ss1 = 0.f;
#pragma unroll
        for (int j = 0; j < 8; ++j) {
            const int col = bn + wn * 64 + j * 8 + r * 2;
            const float b0 = __ldg(&bias[col]);
            const float b1 = __ldg(&bias[col + 1]);
            float2 v0 = make_float2(acc[f][j][0] + b0, acc[f][j][1] + b1);
            float2 v1 = make_float2(acc[f][j][2] + b0, acc[f][j][3] + b1);
            *(float2*)&C[(size_t)row0 * DIMC + col]       = v0;
            *(float2*)&C[(size_t)(row0 + 8) * DIMC + col] = v1;
            ss0 += v0.x * v0.x + v0.y * v0.y;
            ss1 += v1.x * v1.x + v1.y * v1.y;
        }
        if (ss) {
            ss0 += __shfl_xor_sync(0xffffffffu, ss0, 1);
            ss0 += __shfl_xor_sync(0xffffffffu, ss0, 2);
            ss1 += __shfl_xor_sync(0xffffffffu, ss1, 1);
            ss1 += __shfl_xor_sync(0xffffffffu, ss1, 2);
            if (r == 0) {
                atomicAdd(&ss[row0], ss0);
                atomicAdd(&ss[row0 + 8], ss1);
            }
        }
    }
}

// fused QKV: blockIdx.x in [0,24): matrix m = bx>>3, n-block = (bx&7)*128
__global__ __launch_bounds__(128, 2)
void gemm_qkv_kernel(const float* __restrict__ A,
                     const float* __restrict__ Wbase,
                     const float* __restrict__ qb,
                     const float* __restrict__ kb,
                     const float* __restrict__ vb,
                     float* __restrict__ Cq,
                     float* __restrict__ Ck,
                     float* __restrict__ Cv,
                     float* __restrict__ ssq,
                     float* __restrict__ ssk)
{
    extern __shared__ char dsm[];
    const int m  = blockIdx.x >> 3;
    const int bn = (blockIdx.x & 7) * 128;
    const int bm = blockIdx.y * 128;

    const float* W    = Wbase + (size_t)m * (DIMC * DIMC);
    const float* bias = (m == 0) ? qb : (m == 1) ? kb : vb;
    float* C          = (m == 0) ? Cq : (m == 1) ? Ck : Cv;
    float* ss         = (m == 0) ? ssq : (m == 1) ? ssk : nullptr;

    gemm_body(A, W, bias, C, ss, bm, bn, dsm);
}

// single GEMM (output projection)
__global__ __launch_bounds__(128, 2)
void gemm_tc_kernel(const float* __restrict__ A,
                    const float* __restrict__ W,
                    const float* __restrict__ bias,
                    float* __restrict__ C)
{
    extern __shared__ char dsm[];
    gemm_body(A, W, bias, C, nullptr,
              blockIdx.y * 128, blockIdx.x * 128, dsm);
}

// ---------------- zero the sum-of-squares accumulators ----------------------
__global__ void zero_ss_kernel(float* __restrict__ a, float* __restrict__ b)
{
    const int i = blockIdx.x * blockDim.x + threadIdx.x;
    if (i < TROWS) { a[i] = 0.f; b[i] = 0.f; }
}

// ---------------- windowed frame attention w/ fused rmsnorm+rope -----------
// One block (128 thr) per (si, head). 16 frames x 64 dims. Mask: j<=i, i-j<8.
// Output go is stored tf32-rounded (feeds the final GEMM raw-bit path).
__global__ __launch_bounds__(128)
void attn_kernel(const float* __restrict__ q,
                 const float* __restrict__ k,
                 const float* __restrict__ v,
                 float* __restrict__ o,
                 const float* __restrict__ ssq,
                 const float* __restrict__ ssk,
                 const float* __restrict__ nqw,
                 const float* __restrict__ nkw,
                 const float* __restrict__ fcos,
                 const float* __restrict__ fsin)
{
    const int si  = blockIdx.x;
    const int h   = blockIdx.y;
    const int tid = threadIdx.x;

    __shared__ float sq[16][68];   // padded rows: conflict-free column loads
    __shared__ float sk[16][68];
    __shared__ float sv[16][68];
    __shared__ float sS[16][17];
    __shared__ float scq[16], sck[16];
    __shared__ float swq[64], swk[64];

    if (tid < 16) {
        const int t = tid * SQ + si;
        scq[tid] = rsqrtf(ssq[t] * (1.0f / 1024.0f) + 1e-6f);
        sck[tid] = rsqrtf(ssk[t] * (1.0f / 1024.0f) + 1e-6f);
        *(float4*)&swq[tid * 4] = *(const float4*)&nqw[h * HDC + tid * 4];
        *(float4*)&swk[tid * 4] = *(const float4*)&nkw[h * HDC + tid * 4];
    }
    __syncthreads();

    // load q/k/v tiles; apply rmsnorm scale + rope to q,k on the fly
#pragma unroll
    for (int e = tid; e < 256; e += 128) {
        const int f  = e >> 4;
        const int d4 = (e & 15) * 4;
        const int t  = f * SQ + si;
        const size_t base = ((size_t)t) * DIMC + h * HDC + d4;

        const int m0 = d4 >> 1;        // rope pair indices within head
        const int m1 = m0 + 1;
        const float c0 = fcos[(size_t)t * 32 + m0];
        const float s0 = fsin[(size_t)t * 32 + m0];
        const float c1 = fcos[(size_t)t * 32 + m1];
        const float s1 = fsin[(size_t)t * 32 + m1];

        {
            const float4 qv = *(const float4*)&q[base];
            const float a = scq[f];
            const float h0 = qv.x * a * swq[d4 + 0];
            const float h1 = qv.y * a * swq[d4 + 1];
            const float h2 = qv.z * a * swq[d4 + 2];
            const float h3 = qv.w * a * swq[d4 + 3];
            sq[f][d4 + 0] = h0 * c0 - h1 * s0;
            sq[f][d4 + 1] = h0 * s0 + h1 * c0;
            sq[f][d4 + 2] = h2 * c1 - h3 * s1;
            sq[f][d4 + 3] = h2 * s1 + h3 * c1;
        }
        {
            const float4 kv = *(const float4*)&k[base];
            const float a = sck[f];
            const float h0 = kv.x * a * swk[d4 + 0];
            const float h1 = kv.y * a * swk[d4 + 1];
            const float h2 = kv.z * a * swk[d4 + 2];
            const float h3 = kv.w * a * swk[d4 + 3];
            sk[f][d4 + 0] = h0 * c0 - h1 * s0;
            sk[f][d4 + 1] = h0 * s0 + h1 * c0;
            sk[f][d4 + 2] = h2 * c1 - h3 * s1;
            sk[f][d4 + 3] = h2 * s1 + h3 * c1;
        }
        *(float4*)&sv[f][d4] = *(const float4*)&v[base];
    }
    __syncthreads();

    // scores: thread handles (i1, j) and (i1+8, j)
    {
        const int i1 = tid >> 4;       // 0..7
        const int i2 = i1 + 8;         // 8..15
        const int j  = tid & 15;
        float s1 = 0.f, s2 = 0.f;
#pragma unroll
        for (int d = 0; d < 64; d += 4) {
            const float4 kk = *(const float4*)&sk[j][d];
            const float4 q1 = *(const float4*)&sq[i1][d];
            const float4 q2 = *(const float4*)&sq[i2][d];
            s1 += q1.x * kk.x + q1.y * kk.y + q1.z * kk.z + q1.w * kk.w;
            s2 += q2.x * kk.x + q2.y * kk.y + q2.z * kk.z + q2.w * kk.w;
        }
        const bool m1 = (j <= i1) && (i1 - j) < WINDOW;
        const bool m2 = (j <= i2) && (i2 - j) < WINDOW;
        sS[i1][j] = m1 ? s1 * 0.125f : -1e30f;
        sS[i2][j] = m2 ? s2 * 0.125f : -1e30f;
    }
    __syncthreads();

    // softmax per row
    if (tid < 16) {
        const int i = tid;
        float m = -1e30f;
#pragma unroll
        for (int j = 0; j < 16; ++j) m = fmaxf(m, sS[i][j]);
        float e[16];
        float sum = 0.f;
#pragma unroll
        for (int j = 0; j < 16; ++j) { e[j] = expf(sS[i][j] - m); sum += e[j]; }
        const float inv = 1.f / sum;
#pragma unroll
        for (int j = 0; j < 16; ++j) sS[i][j] = e[j] * inv;
    }
    __syncthreads();

    // O = attn @ V : thread owns (i = tid>>3, 8 dims at d0=(tid&7)*8)
    // stored tf32-rounded for the final GEMM
    {
        const int i  = tid >> 3;        // 0..15
        const int d0 = (tid & 7) * 8;   // 0..56
        float4 a0 = make_float4(0.f, 0.f, 0.f, 0.f);
        float4 a1 = make_float4(0.f, 0.f, 0.f, 0.f);
#pragma unroll
        for (int j = 0; j < 16; ++j) {
            const float s  = sS[i][j];
            const float4 v0 = *(const float4*)&sv[j][d0];
            const float4 v1 = *(const float4*)&sv[j][d0 + 4];
            a0.x += s * v0.x; a0.y += s * v0.y; a0.z += s * v0.z; a0.w += s * v0.w;
            a1.x += s * v1.x; a1.y += s * v1.y; a1.z += s * v1.z; a1.w += s * v1.w;
        }
        a0.x = f2tf32f(a0.x); a0.y = f2tf32f(a0.y);
        a0.z = f2tf32f(a0.z); a0.w = f2tf32f(a0.w);
        a1.x = f2tf32f(a1.x); a1.y = f2tf32f(a1.y);
        a1.z = f2tf32f(a1.z); a1.w = f2tf32f(a1.w);
        float* orow = &o[((size_t)(i * SQ + si)) * DIMC + h * HDC + d0];
        *(float4*)&orow[0] = a0;
        *(float4*)&orow[4] = a1;
    }
}

// ---------------- launch ----------------------------------------------------
extern "C" void kernel_launch(void* const* d_in, const int* in_sizes, int n_in,
                              void* d_out, int out_size)
{
    const float* x   = (const float*)d_in[0];
    const float* fc  = (const float*)d_in[1];
    const float* fs  = (const float*)d_in[2];
    const float* q_w = (const float*)d_in[3];
    const float* q_b = (const float*)d_in[4];
    const float* k_w = (const float*)d_in[5];
    const float* k_b = (const float*)d_in[6];
    const float* v_w = (const float*)d_in[7];
    const float* v_b = (const float*)d_in[8];
    const float* o_w = (const float*)d_in[9];
    const float* o_b = (const float*)d_in[10];
    const float* nqw = (const float*)d_in[11];
    const float* nkw = (const float*)d_in[12];
    float* out = (float*)d_out;

    float *gq, *gk, *gv, *go, *gx, *gw, *gssq, *gssk;
    cudaGetSymbolAddress((void**)&gq, g_q);
    cudaGetSymbolAddress((void**)&gk, g_k);
    cudaGetSymbolAddress((void**)&gv, g_v);
    cudaGetSymbolAddress((void**)&go, g_o);
    cudaGetSymbolAddress((void**)&gx, g_x);
    cudaGetSymbolAddress((void**)&gw, g_w);
    cudaGetSymbolAddress((void**)&gssq, g_ssq);
    cudaGetSymbolAddress((void**)&gssk, g_ssk);

    float* gwo = gw + 3 * (size_t)(DIMC * DIMC);

    cudaFuncSetAttribute(gemm_qkv_kernel,
                         cudaFuncAttributeMaxDynamicSharedMemorySize, DSMEM_BYTES);
    cudaFuncSetAttribute(gemm_tc_kernel,
                         cudaFuncAttributeMaxDynamicSharedMemorySize, DSMEM_BYTES);

    // prepass: tf32-round x and the four weight matrices
    const int xw4 = (TROWS * DIMC) / 4;
    const int ww4 = (DIMC * DIMC) / 4;
    round_tf32_kernel<<<(xw4 + 255) / 256, 256>>>(x, gx, xw4);
    round_w_kernel<<<dim3((ww4 + 255) / 256, 4), 256>>>(q_w, k_w, v_w, o_w,
                                                        gw, ww4);
    zero_ss_kernel<<<(TROWS + 255) / 256, 256>>>(gssq, gssk);

    // fused Q,K,V projections: one launch, 24 n-blocks x 184 m-blocks
    gemm_qkv_kernel<<<dim3(24, TROWS / 128), 128, DSMEM_BYTES>>>(
        gx, gw, q_b, k_b, v_b, gq, gk, gv, gssq, gssk);

    attn_kernel<<<dim3(SQ, NHC), 128>>>(gq, gk, gv, go,
                                        gssq, gssk, nqw, nkw, fc, fs);

    gemm_tc_kernel<<<dim3(DIMC / 128, TROWS / 128), 128, DSMEM_BYTES>>>(
        go, gwo, o_b, out);
}

// round 17
// speedup vs baseline: 1.8867x; 1.6388x over previous
#include <cuda_runtime.h>
#include <cuda_fp16.h>
#include <cstdint>
#include <math.h>

// Problem constants (fixed by setup_inputs)
#define DIMC   1024
#define NHC    16
#define HDC    64
#define FQ     16          // frames
#define SQ     1472        // tokens per frame
#define TROWS  (FQ * SQ)   // 23552 total rows
#define WINDOW 8

// ---------------- scratch (device globals; no allocation allowed) ----------
__device__ float  g_q[(size_t)TROWS * DIMC];
__device__ float  g_k[(size_t)TROWS * DIMC];
__device__ float  g_v[(size_t)TROWS * DIMC];
__device__ __half g_o16[(size_t)TROWS * DIMC];   // fp16 attn output
__device__ __half g_x16[(size_t)TROWS * DIMC];   // fp16 x
__device__ __half g_w16[4][DIMC * DIMC];         // fp16 weights q,k,v,o
__device__ float  g_ssq[TROWS];
__device__ float  g_ssk[TROWS];

// =================== helpers ================================================
__device__ __forceinline__ uint32_t smem_u32(const void* p) {
    uint32_t a;
    asm("{ .reg .u64 t; cvta.to.shared.u64 t, %1; cvt.u32.u64 %0, t; }"
        : "=r"(a) : "l"(p));
    return a;
}

#define CP_ASYNC16(dst, src) \
    asm volatile("cp.async.cg.shared.global [%0], [%1], 16;" \
                 :: "r"(dst), "l"(src) : "memory")
#define CP_COMMIT() asm volatile("cp.async.commit_group;" ::: "memory")
#define CP_WAIT(n)  asm volatile("cp.async.wait_group %0;" :: "n"(n) : "memory")

__device__ __forceinline__ uint32_t pack_half2(float a, float b) {
    __half2 h = __floats2half2_rn(a, b);
    return *(uint32_t*)&h;
}

__device__ __forceinline__ void mma_f16(float* c, const uint32_t* a,
                                        const uint32_t* b) {
    asm volatile(
        "mma.sync.aligned.m16n8k16.row.col.f32.f16.f16.f32 "
        "{%0,%1,%2,%3}, {%4,%5,%6,%7}, {%8,%9}, {%0,%1,%2,%3};"
        : "+f"(c[0]), "+f"(c[1]), "+f"(c[2]), "+f"(c[3])
        : "r"(a[0]), "r"(a[1]), "r"(a[2]), "r"(a[3]),
          "r"(b[0]), "r"(b[1]));
}

// ---------------- fp32 -> fp16 prepasses ------------------------------------
__global__ __launch_bounds__(256)
void tofp16_kernel(const float* __restrict__ in, __half* __restrict__ out,
                   int n8)
{
    const int i = blockIdx.x * blockDim.x + threadIdx.x;
    if (i < n8) {
        const float4 u = *(const float4*)&in[(size_t)i * 8];
        const float4 w = *(const float4*)&in[(size_t)i * 8 + 4];
        uint4 o;
        o.x = pack_half2(u.x, u.y);
        o.y = pack_half2(u.z, u.w);
        o.z = pack_half2(w.x, w.y);
        o.w = pack_half2(w.z, w.w);
        *(uint4*)&out[(size_t)i * 8] = o;
    }
}

// batched: convert the 4 weight matrices in one launch (blockIdx.y selects)
__global__ __launch_bounds__(256)
void tofp16_w_kernel(const float* __restrict__ w0, const float* __restrict__ w1,
                     const float* __restrict__ w2, const float* __restrict__ w3,
                     __half* __restrict__ out /* g_w16 base */, int n8)
{
    const int m = blockIdx.y;
    const float* in = (m == 0) ? w0 : (m == 1) ? w1 : (m == 2) ? w2 : w3;
    __half* o = out + (size_t)m * (DIMC * DIMC);
    const int i = blockIdx.x * blockDim.x + threadIdx.x;
    if (i < n8) {
        const float4 u = *(const float4*)&in[(size_t)i * 8];
        const float4 w = *(const float4*)&in[(size_t)i * 8 + 4];
        uint4 v;
        v.x = pack_half2(u.x, u.y);
        v.y = pack_half2(u.z, u.w);
        v.z = pack_half2(w.x, w.y);
        v.w = pack_half2(w.z, w.w);
        *(uint4*)&o[(size_t)i * 8] = v;
    }
}

// =================== mma.sync FP16 GEMM core ================================
// C[128,128] fp32 = A[*,1024] @ W[1024,*]^T + bias, A/W fp16 K-contiguous.
// BK=64 (128-byte rows -> same XOR swizzle as tf32 version), KITERS=16,
// 3-stage cp.async pipeline (distance 2, single barrier per K-tile),
// 128 threads, 4 warps (2x2) of 64x64 tiles, 2 CTAs/SM.
// Fragments register-double-buffered across k16-steps AND across K-tiles.
#define GSTAGES      3
#define KT           64
#define KITERS       (DIMC / KT)             // 16
#define A_TILE_BYTES 16384                   // 128 rows x 64 halves (128B)
#define B_TILE_BYTES 16384
#define STAGE_BYTES  (A_TILE_BYTES + B_TILE_BYTES)   // 32 KB
#define DSMEM_BYTES  (GSTAGES * STAGE_BYTES)         // 96 KB
#define A_TILE_WORDS (A_TILE_BYTES / 4)

__device__ __forceinline__
void gemm_body(const __half* __restrict__ A,
               const __half* __restrict__ W,
               const float* __restrict__ bias,
               float* __restrict__ C,
               float* __restrict__ ss,
               int bm, int bn, char* dsm)
{
    const uint32_t* su = (const uint32_t*)dsm;

    const int tid  = threadIdx.x;
    const int wid  = tid >> 5;
    const int lane = tid & 31;
    const int q    = lane >> 2;   // 0..7
    const int r    = lane & 3;    // 0..3
    const int wm   = wid & 1;     // warp m block (64 rows of 128)
    const int wn   = wid >> 1;    // warp n block (64 cols of 128)

    const uint32_t sbase = smem_u32(dsm);

    float acc[4][8][4];
#pragma unroll
    for (int f = 0; f < 4; ++f)
#pragma unroll
        for (int j = 0; j < 8; ++j)
#pragma unroll
            for (int c = 0; c < 4; ++c) acc[f][j][c] = 0.f;

    // stage loader: A tile 128x64h (1024 x 16B) + B tile same,
    // 128 threads: 8 A-chunks + 8 B-chunks each, swizzled 16B stores
    auto issue_stage = [&](int kt_idx, int buf) {
        const int k0 = kt_idx * KT;
        const uint32_t ab = sbase + buf * STAGE_BYTES;
        const uint32_t bb = ab + A_TILE_BYTES;
#pragma unroll
        for (int it = 0; it < 8; ++it) {
            const int e   = tid + it * 128;    // 0..1023
            const int row = e >> 3;
            const int g   = e & 7;
            const uint32_t off = (uint32_t)(row * 128 + ((g ^ (row & 7)) << 4));
            CP_ASYNC16(ab + off, &A[(size_t)(bm + row) * DIMC + k0 + g * 8]);
            CP_ASYNC16(bb + off, &W[(size_t)(bn + row) * DIMC + k0 + g * 8]);
        }
        CP_COMMIT();
    };

    issue_stage(0, 0);
    issue_stage(1, 1);

    uint32_t afr[2][4][4];
    uint32_t bfr[2][8][2];

    // fragment loader into a slot from tile buffers (sA/sB), k16-chunk c
    // groups: 2c (k=2r,2r+1) and 2c+1 (k=2r+8,2r+9); word r within group.
    auto load_frags = [&](uint32_t (*af)[4], uint32_t (*bf)[2],
                          const uint32_t* sA, const uint32_t* sB, int c) {
        const int sw0 = ((2 * c) ^ q) * 4 + r;
        const int sw1 = ((2 * c + 1) ^ q) * 4 + r;
#pragma unroll
        for (int f = 0; f < 4; ++f) {
            const int row0 = wm * 64 + f * 16 + q;     // row%8 == q
            const int row1 = row0 + 8;
            af[f][0] = sA[row0 * 32 + sw0];
            af[f][1] = sA[row1 * 32 + sw0];
            af[f][2] = sA[row0 * 32 + sw1];
            af[f][3] = sA[row1 * 32 + sw1];
        }
#pragma unroll
        for (int j = 0; j < 8; ++j) {
            const int n0 = wn * 64 + j * 8 + q;        // n%8 == q
            bf[j][0] = sB[n0 * 32 + sw0];
            bf[j][1] = sB[n0 * 32 + sw1];
        }
    };

    int buf_c = 0;   // buffer of current kt
    int buf_p = 2;   // buffer for kt+2
    for (int kt = 0; kt < KITERS; ++kt) {
        if (kt < KITERS - 1) { CP_WAIT(1); } else { CP_WAIT(0); }
        __syncthreads();
        if (kt + 2 < KITERS) issue_stage(kt + 2, buf_p);

        const uint32_t* sA = su + (size_t)buf_c * (STAGE_BYTES / 4);
        const uint32_t* sB = sA + A_TILE_WORDS;

        if (kt == 0)
            load_frags(afr[0], bfr[0], sA, sB, 0);

#pragma unroll
        for (int ks = 0; ks < 4; ++ks) {
            const int cur = ks & 1;
            const int nxt = cur ^ 1;
            if (ks < 3) {
                load_frags(afr[nxt], bfr[nxt], sA, sB, ks + 1);
            } else if (kt + 1 < KITERS) {
                const int buf_n = (buf_c == 2) ? 0 : buf_c + 1;
                const uint32_t* sAn = su + (size_t)buf_n * (STAGE_BYTES / 4);
                const uint32_t* sBn = sAn + A_TILE_WORDS;
                load_frags(afr[nxt], bfr[nxt], sAn, sBn, 0);
            }
#pragma unroll
            for (int f = 0; f < 4; ++f)
#pragma unroll
                for (int j = 0; j < 8; ++j)
                    mma_f16(acc[f][j], afr[cur][f], bfr[cur][j]);
        }

        buf_c = (buf_c == 2) ? 0 : buf_c + 1;
        buf_p = (buf_p == 2) ? 0 : buf_p + 1;
    }

    // epilogue: add bias, store; optional per-row sum-of-squares accumulation
#pragma unroll
    for (int f = 0; f < 4; ++f) {
        const int row0 = bm + wm * 64 + f * 16 + q;
        float ss0 = 0.f, ss1 = 0.f;
#pragma unroll
        for (int j = 0; j < 8; ++j) {
            const int col = bn + wn * 64 + j * 8 + r * 2;
            const float b0 = __ldg(&bias[col]);
            const float b1 = __ldg(&bias[col + 1]);
            float2 v0 = make_float2(acc[f][j][0] + b0, acc[f][j][1] + b1);
            float2 v1 = make_float2(acc[f][j][2] + b0, acc[f][j][3] + b1);
            *(float2*)&C[(size_t)row0 * DIMC + col]       = v0;
            *(float2*)&C[(size_t)(row0 + 8) * DIMC + col] = v1;
            ss0 += v0.x * v0.x + v0.y * v0.y;
            ss1 += v1.x * v1.x + v1.y * v1.y;
        }
        if (ss) {
            ss0 += __shfl_xor_sync(0xffffffffu, ss0, 1);
            ss0 += __shfl_xor_sync(0xffffffffu, ss0, 2);
            ss1 += __shfl_xor_sync(0xffffffffu, ss1, 1);
            ss1 += __shfl_xor_sync(0xffffffffu, ss1, 2);
            if (r == 0) {
                atomicAdd(&ss[row0], ss0);
                atomicAdd(&ss[row0 + 8], ss1);
            }
        }
    }
}

// fused QKV: blockIdx.x in [0,24): matrix m = bx>>3, n-block = (bx&7)*128
__global__ __launch_bounds__(128, 2)
void gemm_qkv_kernel(const __half* __restrict__ A,
                     const __half* __restrict__ Wbase,
                     const float* __restrict__ qb,
                     const float* __restrict__ kb,
                     const float* __restrict__ vb,
                     float* __restrict__ Cq,
                     float* __restrict__ Ck,
                     float* __restrict__ Cv,
                     float* __restrict__ ssq,
                     float* __restrict__ ssk)
{
    extern __shared__ char dsm[];
    const int m  = blockIdx.x >> 3;
    const int bn = (blockIdx.x & 7) * 128;
    const int bm = blockIdx.y * 128;

    const __half* W   = Wbase + (size_t)m * (DIMC * DIMC);
    const float* bias = (m == 0) ? qb : (m == 1) ? kb : vb;
    float* C          = (m == 0) ? Cq : (m == 1) ? Ck : Cv;
    float* ss         = (m == 0) ? ssq : (m == 1) ? ssk : nullptr;

    gemm_body(A, W, bias, C, ss, bm, bn, dsm);
}

// single GEMM (output projection)
__global__ __launch_bounds__(128, 2)
void gemm_tc_kernel(const __half* __restrict__ A,
                    const __half* __restrict__ W,
                    const float* __restrict__ bias,
                    float* __restrict__ C)
{
    extern __shared__ char dsm[];
    gemm_body(A, W, bias, C, nullptr,
              blockIdx.y * 128, blockIdx.x * 128, dsm);
}

// ---------------- zero the sum-of-squares accumulators ----------------------
__global__ void zero_ss_kernel(float* __restrict__ a, float* __restrict__ b)
{
    const int i = blockIdx.x * blockDim.x + threadIdx.x;
    if (i < TROWS) { a[i] = 0.f; b[i] = 0.f; }
}

// ---------------- windowed frame attention w/ fused rmsnorm+rope -----------
// One block (128 thr) per (si, head). 16 frames x 64 dims. Mask: j<=i, i-j<8.
// Output stored as fp16 (feeds the final fp16 GEMM).
__global__ __launch_bounds__(128)
void attn_kernel(const float* __restrict__ q,
                 const float* __restrict__ k,
                 const float* __restrict__ v,
                 __half* __restrict__ o,
                 const float* __restrict__ ssq,
                 const float* __restrict__ ssk,
                 const float* __restrict__ nqw,
                 const float* __restrict__ nkw,
                 const float* __restrict__ fcos,
                 const float* __restrict__ fsin)
{
    const int si  = blockIdx.x;
    const int h   = blockIdx.y;
    const int tid = threadIdx.x;

    __shared__ float sq[16][68];   // padded rows: conflict-free column loads
    __shared__ float sk[16][68];
    __shared__ float sv[16][68];
    __shared__ float sS[16][17];
    __shared__ float scq[16], sck[16];
    __shared__ float swq[64], swk[64];

    if (tid < 16) {
        const int t = tid * SQ + si;
        scq[tid] = rsqrtf(ssq[t] * (1.0f / 1024.0f) + 1e-6f);
        sck[tid] = rsqrtf(ssk[t] * (1.0f / 1024.0f) + 1e-6f);
        *(float4*)&swq[tid * 4] = *(const float4*)&nqw[h * HDC + tid * 4];
        *(float4*)&swk[tid * 4] = *(const float4*)&nkw[h * HDC + tid * 4];
    }
    __syncthreads();

    // load q/k/v tiles; apply rmsnorm scale + rope to q,k on the fly
#pragma unroll
    for (int e = tid; e < 256; e += 128) {
        const int f  = e >> 4;
        const int d4 = (e & 15) * 4;
        const int t  = f * SQ + si;
        const size_t base = ((size_t)t) * DIMC + h * HDC + d4;

        const int m0 = d4 >> 1;        // rope pair indices within head
        const int m1 = m0 + 1;
        const float c0 = fcos[(size_t)t * 32 + m0];
        const float s0 = fsin[(size_t)t * 32 + m0];
        const float c1 = fcos[(size_t)t * 32 + m1];
        const float s1 = fsin[(size_t)t * 32 + m1];

        {
            const float4 qv = *(const float4*)&q[base];
            const float a = scq[f];
            const float h0 = qv.x * a * swq[d4 + 0];
            const float h1 = qv.y * a * swq[d4 + 1];
            const float h2 = qv.z * a * swq[d4 + 2];
            const float h3 = qv.w * a * swq[d4 + 3];
            sq[f][d4 + 0] = h0 * c0 - h1 * s0;
            sq[f][d4 + 1] = h0 * s0 + h1 * c0;
            sq[f][d4 + 2] = h2 * c1 - h3 * s1;
            sq[f][d4 + 3] = h2 * s1 + h3 * c1;
        }
        {
            const float4 kv = *(const float4*)&k[base];
            const float a = sck[f];
            const float h0 = kv.x * a * swk[d4 + 0];
            const float h1 = kv.y * a * swk[d4 + 1];
            const float h2 = kv.z * a * swk[d4 + 2];
            const float h3 = kv.w * a * swk[d4 + 3];
            sk[f][d4 + 0] = h0 * c0 - h1 * s0;
            sk[f][d4 + 1] = h0 * s0 + h1 * c0;
            sk[f][d4 + 2] = h2 * c1 - h3 * s1;
            sk[f][d4 + 3] = h2 * s1 + h3 * c1;
        }
        *(float4*)&sv[f][d4] = *(const float4*)&v[base];
    }
    __syncthreads();

    // scores: thread handles (i1, j) and (i1+8, j)
    {
        const int i1 = tid >> 4;       // 0..7
        const int i2 = i1 + 8;         // 8..15
        const int j  = tid & 15;
        float s1 = 0.f, s2 = 0.f;
#pragma unroll
        for (int d = 0; d < 64; d += 4) {
            const float4 kk = *(const float4*)&sk[j][d];
            const float4 q1 = *(const float4*)&sq[i1][d];
            const float4 q2 = *(const float4*)&sq[i2][d];
            s1 += q1.x * kk.x + q1.y * kk.y + q1.z * kk.z + q1.w * kk.w;
            s2 += q2.x * kk.x + q2.y * kk.y + q2.z * kk.z + q2.w * kk.w;
        }
        const bool m1 = (j <= i1) && (i1 - j) < WINDOW;
        const bool m2 = (j <= i2) && (i2 - j) < WINDOW;
        sS[i1][j] = m1 ? s1 * 0.125f : -1e30f;
        sS[i2][j] = m2 ? s2 * 0.125f : -1e30f;
    }
    __syncthreads();

    // softmax per row
    if (tid < 16) {
        const int i = tid;
        float m = -1e30f;
#pragma unroll
        for (int j = 0; j < 16; ++j) m = fmaxf(m, sS[i][j]);
        float e[16];
        float sum = 0.f;
#pragma unroll
        for (int j = 0; j < 16; ++j) { e[j] = expf(sS[i][j] - m); sum += e[j]; }
        const float inv = 1.f / sum;
#pragma unroll
        for (int j = 0; j < 16; ++j) sS[i][j] = e[j] * inv;
    }
    __syncthreads();

    // O = attn @ V : thread owns (i = tid>>3, 8 dims at d0=(tid&7)*8)
    // stored fp16 for the final GEMM
    {
        const int i  = tid >> 3;        // 0..15
        const int d0 = (tid & 7) * 8;   // 0..56
        float4 a0 = make_float4(0.f, 0.f, 0.f, 0.f);
        float4 a1 = make_float4(0.f, 0.f, 0.f, 0.f);
#pragma unroll
        for (int j = 0; j < 16; ++j) {
            const float s  = sS[i][j];
            const float4 v0 = *(const float4*)&sv[j][d0];
            const float4 v1 = *(const float4*)&sv[j][d0 + 4];
            a0.x += s * v0.x; a0.y += s * v0.y; a0.z += s * v0.z; a0.w += s * v0.w;
            a1.x += s * v1.x; a1.y += s * v1.y; a1.z += s * v1.z; a1.w += s * v1.w;
        }
        uint4 o16;
        o16.x = pack_half2(a0.x, a0.y);
        o16.y = pack_half2(a0.z, a0.w);
        o16.z = pack_half2(a1.x, a1.y);
        o16.w = pack_half2(a1.z, a1.w);
        *(uint4*)&o[((size_t)(i * SQ + si)) * DIMC + h * HDC + d0] = o16;
    }
}

// ---------------- launch ----------------------------------------------------
extern "C" void kernel_launch(void* const* d_in, const int* in_sizes, int n_in,
                              void* d_out, int out_size)
{
    const float* x   = (const float*)d_in[0];
    const float* fc  = (const float*)d_in[1];
    const float* fs  = (const float*)d_in[2];
    const float* q_w = (const float*)d_in[3];
    const float* q_b = (const float*)d_in[4];
    const float* k_w = (const float*)d_in[5];
    const float* k_b = (const float*)d_in[6];
    const float* v_w = (const float*)d_in[7];
    const float* v_b = (const float*)d_in[8];
    const float* o_w = (const float*)d_in[9];
    const float* o_b = (const float*)d_in[10];
    const float* nqw = (const float*)d_in[11];
    const float* nkw = (const float*)d_in[12];
    float* out = (float*)d_out;

    float *gq, *gk, *gv, *gssq, *gssk;
    __half *go16, *gx16, *gw16;
    cudaGetSymbolAddress((void**)&gq, g_q);
    cudaGetSymbolAddress((void**)&gk, g_k);
    cudaGetSymbolAddress((void**)&gv, g_v);
    cudaGetSymbolAddress((void**)&go16, g_o16);
    cudaGetSymbolAddress((void**)&gx16, g_x16);
    cudaGetSymbolAddress((void**)&gw16, g_w16);
    cudaGetSymbolAddress((void**)&gssq, g_ssq);
    cudaGetSymbolAddress((void**)&gssk, g_ssk);

    __half* gwo16 = gw16 + 3 * (size_t)(DIMC * DIMC);

    cudaFuncSetAttribute(gemm_qkv_kernel,
                         cudaFuncAttributeMaxDynamicSharedMemorySize, DSMEM_BYTES);
    cudaFuncSetAttribute(gemm_tc_kernel,
                         cudaFuncAttributeMaxDynamicSharedMemorySize, DSMEM_BYTES);

    // prepass: fp16-convert x and the four weight matrices
    const int xw8 = (TROWS * DIMC) / 8;
    const int ww8 = (DIMC * DIMC) / 8;
    tofp16_kernel<<<(xw8 + 255) / 256, 256>>>(x, gx16, xw8);
    tofp16_w_kernel<<<dim3((ww8 + 255) / 256, 4), 256>>>(q_w, k_w, v_w, o_w,
                                                         gw16, ww8);
    zero_ss_kernel<<<(TROWS + 255) / 256, 256>>>(gssq, gssk);

    // fused Q,K,V projections: one launch, 24 n-blocks x 184 m-blocks
    gemm_qkv_kernel<<<dim3(24, TROWS / 128), 128, DSMEM_BYTES>>>(
        gx16, gw16, q_b, k_b, v_b, gq, gk, gv, gssq, gssk);

    attn_kernel<<<dim3(SQ, NHC), 128>>>(gq, gk, gv, go16,
                                        gssq, gssk, nqw, nkw, fc, fs);

    gemm_tc_kernel<<<dim3(DIMC / 128, TROWS / 128), 128, DSMEM_BYTES>>>(
        go16, gwo16, o_b, out);
}